// round 6
// baseline (speedup 1.0000x reference)
#include <cuda_runtime.h>
#include <cuda_bf16.h>
#include <math.h>
#include <stdint.h>

#define RDIM 8192
#define CDIM 2048
#define HID 20
#define NBLK 32
#define PIT 40   // SMEM row pitch in bf16 halves (80B: 16B-aligned rows, ldmatrix conflict-free)
#define BK 32

// ---------------- device scratch ----------------
__device__ float g_G   [(size_t)RDIM * CDIM];
__device__ float g_P0  [(size_t)RDIM * CDIM];
__device__ float g_B   [(size_t)RDIM * CDIM];
__device__ float g_A   [(size_t)CDIM * CDIM];
__device__ float g_As  [(size_t)CDIM * CDIM];
__device__ float g_Gram[(size_t)CDIM * CDIM];
__device__ float g_Rinv[(size_t)CDIM * CDIM];
__device__ float g_T   [(size_t)1024 * 1024];
__device__ float g_rowp[16 * (size_t)RDIM];
__device__ float g_dL[RDIM];
__device__ float g_dR[CDIM];
__device__ float g_lraw[RDIM];
__device__ float g_rraw[CDIM];
__device__ float g_partL[32];
__device__ float g_partR[8];
__device__ float g_means[2];
__device__ float g_Lv[RDIM];
__device__ float g_Rv[CDIM];

// ---------------- tensor-core helpers ----------------
__device__ __forceinline__ void mma_bf16(float* c, const unsigned* a, const unsigned* b) {
    asm volatile(
        "mma.sync.aligned.m16n8k16.row.col.f32.bf16.bf16.f32 "
        "{%0,%1,%2,%3},{%4,%5,%6,%7},{%8,%9},{%0,%1,%2,%3};"
        : "+f"(c[0]), "+f"(c[1]), "+f"(c[2]), "+f"(c[3])
        : "r"(a[0]), "r"(a[1]), "r"(a[2]), "r"(a[3]), "r"(b[0]), "r"(b[1]));
}

__device__ __forceinline__ unsigned s2u(const void* p) {
    return (unsigned)__cvta_generic_to_shared(p);
}

__device__ __forceinline__ void ldsm4(unsigned* d, unsigned a) {
    asm volatile("ldmatrix.sync.aligned.m8n8.x4.shared.b16 {%0,%1,%2,%3},[%4];"
        : "=r"(d[0]), "=r"(d[1]), "=r"(d[2]), "=r"(d[3]) : "r"(a));
}
__device__ __forceinline__ void ldsm2(unsigned* d, unsigned a) {
    asm volatile("ldmatrix.sync.aligned.m8n8.x2.shared.b16 {%0,%1},[%2];"
        : "=r"(d[0]), "=r"(d[1]) : "r"(a));
}

__device__ __forceinline__ unsigned pack_bf2(__nv_bfloat16 a, __nv_bfloat16 b) {
    return (unsigned)__bfloat16_as_ushort(a) | ((unsigned)__bfloat16_as_ushort(b) << 16);
}

__device__ __forceinline__ void split4(const float* x, uint2& h, uint2& l) {
    __nv_bfloat16 h0 = __float2bfloat16(x[0]);
    __nv_bfloat16 h1 = __float2bfloat16(x[1]);
    __nv_bfloat16 h2 = __float2bfloat16(x[2]);
    __nv_bfloat16 h3 = __float2bfloat16(x[3]);
    h.x = pack_bf2(h0, h1);
    h.y = pack_bf2(h2, h3);
    l.x = pack_bf2(__float2bfloat16(x[0] - __bfloat162float(h0)),
                   __float2bfloat16(x[1] - __bfloat162float(h1)));
    l.y = pack_bf2(__float2bfloat16(x[2] - __bfloat162float(h2)),
                   __float2bfloat16(x[3] - __bfloat162float(h3)));
}

// shared consumption: two k16 chunks via ldmatrix + 3-pass split MMA
__device__ __forceinline__ void consume_tile(
    const __nv_bfloat16* Ah, const __nv_bfloat16* Al,
    const __nv_bfloat16* Bh, const __nv_bfloat16* Bl,
    int wm, int wn, int lane, float acc[4][4][4])
{
    int ar = lane & 15, ac = (lane >> 4) * 8;
    int br = lane & 7,  bc = ((lane >> 3) & 1) * 8;
#pragma unroll
    for (int ch = 0; ch < 2; ch++) {
        int ck = ch * 16;
        unsigned afh[4][4], afl[4][4], bfh[4][2], bfl[4][2];
#pragma unroll
        for (int mi = 0; mi < 4; mi++) {
            ldsm4(afh[mi], s2u(&Ah[(wm + mi * 16 + ar) * PIT + ck + ac]));
            ldsm4(afl[mi], s2u(&Al[(wm + mi * 16 + ar) * PIT + ck + ac]));
        }
#pragma unroll
        for (int ni = 0; ni < 4; ni++) {
            ldsm2(bfh[ni], s2u(&Bh[(wn + ni * 8 + br) * PIT + ck + bc]));
            ldsm2(bfl[ni], s2u(&Bl[(wn + ni * 8 + br) * PIT + ck + bc]));
        }
#pragma unroll
        for (int mi = 0; mi < 4; mi++)
#pragma unroll
            for (int ni = 0; ni < 4; ni++) {
                mma_bf16(acc[mi][ni], afh[mi], bfh[ni]);
                mma_bf16(acc[mi][ni], afh[mi], bfl[ni]);
                mma_bf16(acc[mi][ni], afl[mi], bfh[ni]);
            }
    }
}

// ---------------- tensor GEMM: C = alpha * A^T B (+ Cin) ----------------
// column-major. A: K x M (lda, k-contiguous), B: K x N (ldb). M,N mult of 128, K mult of 32.
__global__ __launch_bounds__(256) void tgemm_tn(
    const float* __restrict__ A, int lda, const float* __restrict__ B, int ldb,
    const float* __restrict__ Cin, float* __restrict__ Cout, int ldc,
    int K, float alpha, int upperOnly)
{
    int p0 = blockIdx.x * 128, q0 = blockIdx.y * 128;
    if (upperOnly && q0 < p0) return;
    __shared__ __align__(16) __nv_bfloat16 Ah[128 * PIT], Al[128 * PIT], Bh[128 * PIT], Bl[128 * PIT];
    int tid = threadIdx.x, lane = tid & 31, warp = tid >> 5;
    int wm = (warp >> 2) * 64, wn = (warp & 3) * 32;
    int g = lane >> 2, tg = lane & 3;
    float acc[4][4][4];
#pragma unroll
    for (int i = 0; i < 4; i++)
#pragma unroll
        for (int j = 0; j < 4; j++)
#pragma unroll
            for (int k = 0; k < 4; k++) acc[i][j][k] = 0.f;

    int row = tid >> 1, ks = (tid & 1) * 16;
    const float* pA = A + (size_t)(p0 + row) * lda + ks;
    const float* pB = B + (size_t)(q0 + row) * ldb + ks;
    float4 ra[4], rb[4];
#pragma unroll
    for (int j = 0; j < 4; j++) { ra[j] = *(const float4*)(pA + 4 * j); rb[j] = *(const float4*)(pB + 4 * j); }

    for (int k0 = 0; k0 < K; k0 += BK) {
        uint2 h, l;
#pragma unroll
        for (int j = 0; j < 4; j++) {
            split4((const float*)&ra[j], h, l);
            *(uint2*)&Ah[row * PIT + ks + 4 * j] = h;
            *(uint2*)&Al[row * PIT + ks + 4 * j] = l;
            split4((const float*)&rb[j], h, l);
            *(uint2*)&Bh[row * PIT + ks + 4 * j] = h;
            *(uint2*)&Bl[row * PIT + ks + 4 * j] = l;
        }
        __syncthreads();
        int kn = k0 + BK;
        if (kn < K) {
#pragma unroll
            for (int j = 0; j < 4; j++) {
                ra[j] = *(const float4*)(pA + kn + 4 * j);
                rb[j] = *(const float4*)(pB + kn + 4 * j);
            }
        }
        consume_tile(Ah, Al, Bh, Bl, wm, wn, lane, acc);
        __syncthreads();
    }
#pragma unroll
    for (int mi = 0; mi < 4; mi++)
#pragma unroll
        for (int ni = 0; ni < 4; ni++) {
            int p = p0 + wm + mi * 16 + g;
            int q = q0 + wn + ni * 8 + 2 * tg;
            float* c = acc[mi][ni];
            size_t o00 = (size_t)q * ldc + p;
            size_t o01 = (size_t)(q + 1) * ldc + p;
            float v00 = alpha * c[0], v01 = alpha * c[1];
            float v10 = alpha * c[2], v11 = alpha * c[3];
            if (Cin) { v00 += Cin[o00]; v01 += Cin[o01]; v10 += Cin[o00 + 8]; v11 += Cin[o01 + 8]; }
            Cout[o00] = v00; Cout[o01] = v01; Cout[o00 + 8] = v10; Cout[o01 + 8] = v11;
        }
}

// ---------------- tensor GEMM: C = gamma*(A*S) + alpha*X + beta*Y ----------------
// A: M x K col-major (m-contiguous, lda), S: K x N col-major (k-contiguous, lds).
__global__ __launch_bounds__(256) void tgemm_nn(
    const float* __restrict__ A, int lda, const float* __restrict__ S, int lds,
    const float* __restrict__ X, float alpha, const float* __restrict__ Y, float beta,
    float gamma, float* __restrict__ Cout, int ldc, int K, int triK)
{
    int i0 = blockIdx.x * 128, q0 = blockIdx.y * 128;
    int kmax = triK ? (q0 + 128) : K;
    if (kmax > K) kmax = K;
    __shared__ __align__(16) __nv_bfloat16 Ah[128 * PIT], Al[128 * PIT], Bh[128 * PIT], Bl[128 * PIT];
    int tid = threadIdx.x, lane = tid & 31, warp = tid >> 5;
    int wm = (warp >> 2) * 64, wn = (warp & 3) * 32;
    int g = lane >> 2, tg = lane & 3;
    float acc[4][4][4];
#pragma unroll
    for (int i = 0; i < 4; i++)
#pragma unroll
        for (int j = 0; j < 4; j++)
#pragma unroll
            for (int k = 0; k < 4; k++) acc[i][j][k] = 0.f;

    int row = tid >> 1, ks = (tid & 1) * 16;
    const float* pS = S + (size_t)(q0 + row) * lds + ks;
    float ra[16];
    float4 rb[4];
#pragma unroll
    for (int j = 0; j < 16; j++) ra[j] = A[(size_t)(ks + j) * lda + i0 + row];
#pragma unroll
    for (int j = 0; j < 4; j++) rb[j] = *(const float4*)(pS + 4 * j);

    for (int k0 = 0; k0 < kmax; k0 += BK) {
        uint2 h, l;
#pragma unroll
        for (int j = 0; j < 4; j++) {
            split4(ra + 4 * j, h, l);
            *(uint2*)&Ah[row * PIT + ks + 4 * j] = h;
            *(uint2*)&Al[row * PIT + ks + 4 * j] = l;
            split4((const float*)&rb[j], h, l);
            *(uint2*)&Bh[row * PIT + ks + 4 * j] = h;
            *(uint2*)&Bl[row * PIT + ks + 4 * j] = l;
        }
        __syncthreads();
        int kn = k0 + BK;
        if (kn < kmax) {
#pragma unroll
            for (int j = 0; j < 16; j++) ra[j] = A[(size_t)(kn + ks + j) * lda + i0 + row];
#pragma unroll
            for (int j = 0; j < 4; j++) rb[j] = *(const float4*)(pS + kn + 4 * j);
        }
        consume_tile(Ah, Al, Bh, Bl, wm, wn, lane, acc);
        __syncthreads();
    }
#pragma unroll
    for (int mi = 0; mi < 4; mi++)
#pragma unroll
        for (int ni = 0; ni < 4; ni++) {
            int p = i0 + wm + mi * 16 + g;
            int q = q0 + wn + ni * 8 + 2 * tg;
            float* c = acc[mi][ni];
            size_t o00 = (size_t)q * ldc + p;
            size_t o01 = (size_t)(q + 1) * ldc + p;
            float v00 = gamma * c[0], v01 = gamma * c[1];
            float v10 = gamma * c[2], v11 = gamma * c[3];
            if (X) { v00 += alpha * X[o00]; v01 += alpha * X[o01]; v10 += alpha * X[o00 + 8]; v11 += alpha * X[o01 + 8]; }
            if (Y) { v00 += beta * Y[o00]; v01 += beta * Y[o01]; v10 += beta * Y[o00 + 8]; v11 += beta * Y[o01 + 8]; }
            Cout[o00] = v00; Cout[o01] = v01; Cout[o00 + 8] = v10; Cout[o01 + 8] = v11;
        }
}

// ---------------- FFMA GEMM (A^T x B) for Cholesky trailing updates ----------------
__global__ __launch_bounds__(256) void gemm_tn(
    const float* __restrict__ A, int lda, const float* __restrict__ B, int ldb,
    const float* __restrict__ Cin, float* __restrict__ Cout, int ldc,
    int K, float alpha, int upperOnly)
{
    int p0 = blockIdx.x * 64, q0 = blockIdx.y * 64;
    if (upperOnly && q0 < p0) return;
    __shared__ float As[16][68];
    __shared__ float Bs[16][68];
    int tid = threadIdx.x, tx = tid & 15, ty = tid >> 4;
    float acc[4][4];
#pragma unroll
    for (int a = 0; a < 4; a++)
#pragma unroll
        for (int b = 0; b < 4; b++) acc[a][b] = 0.f;
    for (int k0 = 0; k0 < K; k0 += 16) {
#pragma unroll
        for (int s2 = 0; s2 < 4; s2++) {
            int idx = tid + s2 * 256;
            int kk = idx & 15, pp = idx >> 4;
            As[kk][pp] = A[(size_t)(p0 + pp) * lda + (k0 + kk)];
            Bs[kk][pp] = B[(size_t)(q0 + pp) * ldb + (k0 + kk)];
        }
        __syncthreads();
#pragma unroll
        for (int kk = 0; kk < 16; kk++) {
            float4 av = *(const float4*)&As[kk][ty * 4];
            float4 bv = *(const float4*)&Bs[kk][tx * 4];
            float ar[4] = {av.x, av.y, av.z, av.w};
            float br[4] = {bv.x, bv.y, bv.z, bv.w};
#pragma unroll
            for (int a = 0; a < 4; a++)
#pragma unroll
                for (int b = 0; b < 4; b++)
                    acc[a][b] = fmaf(ar[a], br[b], acc[a][b]);
        }
        __syncthreads();
    }
#pragma unroll
    for (int a = 0; a < 4; a++)
#pragma unroll
        for (int b = 0; b < 4; b++) {
            int p = p0 + ty * 4 + a, q = q0 + tx * 4 + b;
            size_t o = (size_t)q * ldc + p;
            float v = alpha * acc[a][b];
            if (Cin) v += Cin[o];
            Cout[o] = v;
        }
}

// ---------------- batched FFMA NN GEMM for recursive triangular inverse ----------------
__global__ __launch_bounds__(256) void gemm_nn_b(
    const float* __restrict__ A, long long sA, int lda,
    const float* __restrict__ B, long long sB, int ldb,
    float* __restrict__ C, long long sC, int ldc, int K, float sgn)
{
    const float* Ap = A + (size_t)blockIdx.z * sA;
    const float* Bp = B + (size_t)blockIdx.z * sB;
    float* Cp = C + (size_t)blockIdx.z * sC;
    int i0 = blockIdx.x * 64, q0 = blockIdx.y * 64;
    __shared__ float As[16][68];
    __shared__ float Bs[16][68];
    int tid = threadIdx.x, tx = tid & 15, ty = tid >> 4;
    float acc[4][4];
#pragma unroll
    for (int a = 0; a < 4; a++)
#pragma unroll
        for (int b = 0; b < 4; b++) acc[a][b] = 0.f;
    for (int k0 = 0; k0 < K; k0 += 16) {
#pragma unroll
        for (int s2 = 0; s2 < 4; s2++) {
            int idx = tid + s2 * 256;
            int ii = idx & 63, kk = idx >> 6;
            As[kk][ii] = Ap[(size_t)(k0 + kk) * lda + (i0 + ii)];
            int kk2 = idx & 15, qq = idx >> 4;
            Bs[kk2][qq] = Bp[(size_t)(q0 + qq) * ldb + (k0 + kk2)];
        }
        __syncthreads();
#pragma unroll
        for (int kk = 0; kk < 16; kk++) {
            float4 av = *(const float4*)&As[kk][ty * 4];
            float4 bv = *(const float4*)&Bs[kk][tx * 4];
            float ar[4] = {av.x, av.y, av.z, av.w};
            float br[4] = {bv.x, bv.y, bv.z, bv.w};
#pragma unroll
            for (int a = 0; a < 4; a++)
#pragma unroll
                for (int b = 0; b < 4; b++)
                    acc[a][b] = fmaf(ar[a], br[b], acc[a][b]);
        }
        __syncthreads();
    }
#pragma unroll
    for (int a = 0; a < 4; a++)
#pragma unroll
        for (int b = 0; b < 4; b++) {
            int p = i0 + ty * 4 + a, q = q0 + tx * 4 + b;
            Cp[(size_t)q * ldc + p] = sgn * acc[a][b];
        }
}

// ---------------- small kernels ----------------
__global__ void zeroBufK(float* p) { p[(size_t)blockIdx.x * 256 + threadIdx.x] = 0.f; }

__global__ void symK(const float* __restrict__ in, float* __restrict__ outp) {
    int idx = blockIdx.x * 256 + threadIdx.x;
    int p = idx & (CDIM - 1), q = idx >> 11;
    outp[idx] = 0.5f * (in[idx] + in[(size_t)p * CDIM + q]);
}

__global__ void rowsqK() {
    int i = blockIdx.x * 256 + threadIdx.x;
    int q0 = blockIdx.y * (CDIM / 16);
    float acc = 0.f;
    for (int q = q0; q < q0 + CDIM / 16; q++) {
        float v = g_G[(size_t)q * RDIM + i];
        acc += v * v;
    }
    g_rowp[(size_t)blockIdx.y * RDIM + i] = acc;
}
__global__ void rowcombK() {
    int i = blockIdx.x * 256 + threadIdx.x;
    float s = 0.f;
    for (int ch = 0; ch < 16; ch++) s += g_rowp[(size_t)ch * RDIM + i];
    g_dL[i] = s / (float)CDIM;
}
__global__ void colsqK() {
    __shared__ float red[256];
    int q = blockIdx.x, tid = threadIdx.x;
    const float* col = g_G + (size_t)q * RDIM;
    float acc = 0.f;
    for (int i = tid; i < RDIM; i += 256) { float v = col[i]; acc += v * v; }
    red[tid] = acc; __syncthreads();
    for (int s = 128; s > 0; s >>= 1) { if (tid < s) red[tid] += red[tid + s]; __syncthreads(); }
    if (tid == 0) g_dR[q] = red[0] / (float)RDIM;
}

__device__ __forceinline__ float sigm(float x) { return 1.f / (1.f + expf(-x)); }

__global__ __launch_bounds__(256) void lstmK(
    int N, const float* __restrict__ diag,
    const float* __restrict__ h0, const float* __restrict__ c0,
    const float* __restrict__ Wih0, const float* __restrict__ Whh0,
    const float* __restrict__ bih0, const float* __restrict__ bhh0,
    const float* __restrict__ Wih1, const float* __restrict__ Whh1,
    const float* __restrict__ bih1, const float* __restrict__ bhh1,
    const float* __restrict__ LW, const float* __restrict__ Lb,
    float* __restrict__ raw, float* __restrict__ part)
{
    __shared__ float sWih0[80], sB0[80], sB1[80];
    __shared__ float sWhh0[1600], sWih1[1600], sWhh1[1600];
    __shared__ float sLW[HID];
    int tid = threadIdx.x;
    for (int k = tid; k < 80; k += 256) {
        sWih0[k] = Wih0[k];
        sB0[k] = bih0[k] + bhh0[k];
        sB1[k] = bih1[k] + bhh1[k];
    }
    for (int k = tid; k < 1600; k += 256) {
        sWhh0[k] = Whh0[k]; sWih1[k] = Wih1[k]; sWhh1[k] = Whh1[k];
    }
    if (tid < HID) sLW[tid] = LW[tid];
    __syncthreads();

    int n = blockIdx.x * 256 + tid;
    float d = diag[n];
    float x = logf(fabsf(d)) * 0.1f;
    x = fminf(fmaxf(x, -1.f), 1.f);

    float hp[HID], h1[HID];
    const float* h0p = h0 + (size_t)n * HID;
    const float* c0p = c0 + (size_t)n * HID;
#pragma unroll
    for (int j = 0; j < HID; j++) hp[j] = h0p[j];
    for (int jh = 0; jh < HID; jh++) {
        float gi = sB0[jh]      + sWih0[jh] * x;
        float gf = sB0[20 + jh] + sWih0[20 + jh] * x;
        float gg = sB0[40 + jh] + sWih0[40 + jh] * x;
        float go = sB0[60 + jh] + sWih0[60 + jh] * x;
#pragma unroll
        for (int j = 0; j < HID; j++) {
            float hv = hp[j];
            gi = fmaf(sWhh0[jh * 20 + j], hv, gi);
            gf = fmaf(sWhh0[(20 + jh) * 20 + j], hv, gf);
            gg = fmaf(sWhh0[(40 + jh) * 20 + j], hv, gg);
            go = fmaf(sWhh0[(60 + jh) * 20 + j], hv, go);
        }
        float cc = sigm(gf) * c0p[jh] + sigm(gi) * tanhf(gg);
        h1[jh] = sigm(go) * tanhf(cc);
    }
    const float* h1p = h0 + (size_t)N * HID + (size_t)n * HID;
    const float* c1p = c0 + (size_t)N * HID + (size_t)n * HID;
    float hb[HID];
#pragma unroll
    for (int j = 0; j < HID; j++) hb[j] = h1p[j];
    float o = 0.f;
    for (int jh = 0; jh < HID; jh++) {
        float gi = sB1[jh], gf = sB1[20 + jh], gg = sB1[40 + jh], go = sB1[60 + jh];
#pragma unroll
        for (int j = 0; j < HID; j++) {
            float a = h1[j], b = hb[j];
            gi = fmaf(sWih1[jh * 20 + j], a, fmaf(sWhh1[jh * 20 + j], b, gi));
            gf = fmaf(sWih1[(20 + jh) * 20 + j], a, fmaf(sWhh1[(20 + jh) * 20 + j], b, gf));
            gg = fmaf(sWih1[(40 + jh) * 20 + j], a, fmaf(sWhh1[(40 + jh) * 20 + j], b, gg));
            go = fmaf(sWih1[(60 + jh) * 20 + j], a, fmaf(sWhh1[(60 + jh) * 20 + j], b, go));
        }
        float cc = sigm(gf) * c1p[jh] + sigm(gi) * tanhf(gg);
        float h2 = sigm(go) * tanhf(cc);
        o = fmaf(sLW[jh], h2, o);
    }
    float val = (o + Lb[0]) * 0.1f;
    raw[n] = val;

    __shared__ float red[256];
    red[tid] = val; __syncthreads();
    for (int s = 128; s > 0; s >>= 1) { if (tid < s) red[tid] += red[tid + s]; __syncthreads(); }
    if (tid == 0) part[blockIdx.x] = red[0];
}

__global__ void meansK() {
    if (threadIdx.x == 0) {
        float s = 0.f; for (int i = 0; i < 32; i++) s += g_partL[i];
        g_means[0] = s / (float)RDIM;
        float t = 0.f; for (int i = 0; i < 8; i++) t += g_partR[i];
        g_means[1] = t / (float)CDIM;
    }
}

__global__ void applyK(const float* __restrict__ raw, const float* __restrict__ before,
                       int mi, float* __restrict__ outv) {
    int i = blockIdx.x * 256 + threadIdx.x;
    outv[i] = fmaxf(raw[i] - g_means[mi] + 1.0f, before[i]);
}

__global__ void p0K() {
    size_t idx = (size_t)blockIdx.x * 256 + threadIdx.x;
    int i = (int)(idx & (RDIM - 1));
    int q = (int)(idx >> 13);
    g_P0[idx] = g_Lv[i] * g_G[idx] * g_Rv[q];
}

// ---------------- Cholesky ----------------
__global__ void cholDiagK(int k0) {
    __shared__ float S[64][65];
    int t = threadIdx.x;
    for (int e = t; e < 4096; e += 64) {
        int a = e & 63, b = e >> 6;
        S[a][b] = g_Gram[(size_t)(k0 + b) * CDIM + (k0 + a)];
    }
    __syncthreads();
    for (int j = 0; j < 64; j++) {
        if (t == 0) S[j][j] = sqrtf(S[j][j]);
        __syncthreads();
        float rjj = S[j][j];
        if (t > j) S[j][t] /= rjj;
        __syncthreads();
        if (t > j) {
            float sjt = S[j][t];
            for (int a = j + 1; a <= t; a++) S[a][t] -= S[j][a] * sjt;
        }
        __syncthreads();
    }
    for (int e = t; e < 4096; e += 64) {
        int a = e & 63, b = e >> 6;
        if (a <= b) g_Gram[(size_t)(k0 + b) * CDIM + (k0 + a)] = S[a][b];
    }
}

__global__ void cholTrsmK(int k0) {
    __shared__ float Rkk[64][65];
    __shared__ float Xs[64][65];
    int t = threadIdx.x;
    int qb = k0 + 64 + blockIdx.x * 64;
    for (int e = t; e < 4096; e += 64) {
        int a = e & 63, b = e >> 6;
        Rkk[a][b] = g_Gram[(size_t)(k0 + b) * CDIM + (k0 + a)];
        Xs[a][b]  = g_Gram[(size_t)(qb + b) * CDIM + (k0 + a)];
    }
    __syncthreads();
    for (int a = 0; a < 64; a++) {
        float sum = 0.f;
        for (int b = 0; b < a; b++) sum = fmaf(Rkk[b][a], Xs[b][t], sum);
        Xs[a][t] = (Xs[a][t] - sum) / Rkk[a][a];
    }
    __syncthreads();
    for (int e = t; e < 4096; e += 64) {
        int a = e & 63, b = e >> 6;
        g_Gram[(size_t)(qb + b) * CDIM + (k0 + a)] = Xs[a][b];
    }
}

__global__ void invDiagK() {
    int k0 = blockIdx.x * 64;
    __shared__ float U[64][65];
    __shared__ float Xs[64][65];
    int t = threadIdx.x;
    for (int e = t; e < 4096; e += 64) {
        int a = e & 63, b = e >> 6;
        U[a][b] = (a <= b) ? g_Gram[(size_t)(k0 + b) * CDIM + (k0 + a)] : 0.f;
        Xs[a][b] = 0.f;
    }
    __syncthreads();
    for (int a = 63; a >= 0; a--) {
        if (a <= t) {
            float sum = (a == t) ? 1.f : 0.f;
            for (int b = a + 1; b <= t; b++) sum = fmaf(-U[a][b], Xs[b][t], sum);
            Xs[a][t] = sum / U[a][a];
        }
    }
    __syncthreads();
    for (int e = t; e < 4096; e += 64) {
        int a = e & 63, b = e >> 6;
        g_Rinv[(size_t)(k0 + b) * CDIM + (k0 + a)] = Xs[a][b];
    }
}

extern "C" void kernel_launch(void* const* d_in, const int* in_sizes, int n_in,
                              void* d_out, int out_size) {
    const float* s   = (const float*)d_in[0];
    const float* sg  = (const float*)d_in[1];
    const float* Lh0 = (const float*)d_in[2];
    const float* Lc0 = (const float*)d_in[3];
    const float* Rh0 = (const float*)d_in[4];
    const float* Rc0 = (const float*)d_in[5];
    const float* Lbef = (const float*)d_in[6];
    const float* Rbef = (const float*)d_in[7];
    const float* Wih0 = (const float*)d_in[8];
    const float* Whh0 = (const float*)d_in[9];
    const float* bih0 = (const float*)d_in[10];
    const float* bhh0 = (const float*)d_in[11];
    const float* Wih1 = (const float*)d_in[12];
    const float* Whh1 = (const float*)d_in[13];
    const float* bih1 = (const float*)d_in[14];
    const float* bhh1 = (const float*)d_in[15];
    const float* LW = (const float*)d_in[16];
    const float* Lb = (const float*)d_in[17];
    const float* RW = (const float*)d_in[18];
    const float* Rb = (const float*)d_in[19];
    float* out = (float*)d_out;

    float *gG, *gP0, *gB, *gA, *gAs, *gGram, *gRinv, *gT;
    float *gdL, *gdR, *glraw, *grraw, *gpartL, *gpartR, *gLv, *gRv;
    cudaGetSymbolAddress((void**)&gG, g_G);
    cudaGetSymbolAddress((void**)&gP0, g_P0);
    cudaGetSymbolAddress((void**)&gB, g_B);
    cudaGetSymbolAddress((void**)&gA, g_A);
    cudaGetSymbolAddress((void**)&gAs, g_As);
    cudaGetSymbolAddress((void**)&gGram, g_Gram);
    cudaGetSymbolAddress((void**)&gRinv, g_Rinv);
    cudaGetSymbolAddress((void**)&gT, g_T);
    cudaGetSymbolAddress((void**)&gdL, g_dL);
    cudaGetSymbolAddress((void**)&gdR, g_dR);
    cudaGetSymbolAddress((void**)&glraw, g_lraw);
    cudaGetSymbolAddress((void**)&grraw, g_rraw);
    cudaGetSymbolAddress((void**)&gpartL, g_partL);
    cudaGetSymbolAddress((void**)&gpartR, g_partR);
    cudaGetSymbolAddress((void**)&gLv, g_Lv);
    cudaGetSymbolAddress((void**)&gRv, g_Rv);

    // A = M^T * (0.1*Mgrad)
    tgemm_tn<<<dim3(16, 16), 256>>>(s, RDIM, sg, RDIM, nullptr, gA, CDIM, RDIM, 0.1f, 0);
    symK<<<CDIM * CDIM / 256, 256>>>(gA, gAs);
    // G = 0.1*Mgrad - M*As
    tgemm_nn<<<dim3(64, 16), 256>>>(s, RDIM, gAs, CDIM, sg, 0.1f, nullptr, 0.f, -1.f, gG, RDIM, CDIM, 0);
    // Gram diagonals
    rowsqK<<<dim3(32, 16), 256>>>();
    rowcombK<<<32, 256>>>();
    colsqK<<<CDIM, 256>>>();
    // LSTMs
    lstmK<<<32, 256>>>(RDIM, gdL, Lh0, Lc0, Wih0, Whh0, bih0, bhh0, Wih1, Whh1, bih1, bhh1, LW, Lb, glraw, gpartL);
    lstmK<<<8, 256>>>(CDIM, gdR, Rh0, Rc0, Wih0, Whh0, bih0, bhh0, Wih1, Whh1, bih1, bhh1, RW, Rb, grraw, gpartR);
    meansK<<<1, 32>>>();
    applyK<<<32, 256>>>(glraw, Lbef, 0, gLv);
    applyK<<<8, 256>>>(grraw, Rbef, 1, gRv);
    // P0 = Lv . G . Rv
    p0K<<<(unsigned)((size_t)RDIM * CDIM / 256), 256>>>();
    // A2 = M^T*P0 ; As2 = sym ; B = M*As2 + s - P0
    tgemm_tn<<<dim3(16, 16), 256>>>(s, RDIM, gP0, RDIM, nullptr, gA, CDIM, RDIM, 1.f, 0);
    symK<<<CDIM * CDIM / 256, 256>>>(gA, gAs);
    tgemm_nn<<<dim3(64, 16), 256>>>(s, RDIM, gAs, CDIM, s, 1.f, gP0, -1.f, 1.f, gB, RDIM, CDIM, 0);
    // Gram = B^T B (upper)
    tgemm_tn<<<dim3(16, 16), 256>>>(gB, RDIM, gB, RDIM, nullptr, gGram, CDIM, RDIM, 1.f, 1);
    // blocked Cholesky
    for (int k = 0; k < NBLK; k++) {
        cholDiagK<<<1, 64>>>(k * 64);
        int nb = NBLK - 1 - k;
        if (nb > 0) {
            cholTrsmK<<<nb, 64>>>(k * 64);
            int r0 = (k + 1) * 64;
            const float* panel = gGram + (size_t)r0 * CDIM + k * 64;
            float* base = gGram + (size_t)r0 * CDIM + r0;
            gemm_tn<<<dim3(nb, nb), 256>>>(panel, CDIM, panel, CDIM, base, base, CDIM, 64, -1.f, 1);
        }
    }
    // Rinv via recursive doubling
    zeroBufK<<<CDIM * CDIM / 256, 256>>>(gRinv);
    invDiagK<<<NBLK, 64>>>();
    for (int b = 64; b <= 1024; b *= 2) {
        int npairs = CDIM / (2 * b);
        dim3 g1(b / 64, b / 64, npairs);
        long long strideP = (long long)2 * b * (CDIM + 1);
        gemm_nn_b<<<g1, 256>>>(gGram + (size_t)b * CDIM, strideP, CDIM,
                               gRinv + (size_t)b * CDIM + b, strideP, CDIM,
                               gT, (long long)b * b, b, b, 1.f);
        gemm_nn_b<<<g1, 256>>>(gRinv, strideP, CDIM,
                               gT, (long long)b * b, b,
                               gRinv + (size_t)b * CDIM, strideP, CDIM, b, -1.f);
    }
    // Q = B * Rinv -> out
    tgemm_nn<<<dim3(64, 16), 256>>>(gB, RDIM, gRinv, CDIM, nullptr, 0.f, nullptr, 0.f, 1.f, out, RDIM, CDIM, 1);
}

// round 10
// speedup vs baseline: 1.0907x; 1.0907x over previous
#include <cuda_runtime.h>
#include <cuda_bf16.h>
#include <math.h>
#include <stdint.h>

#define RDIM 8192
#define CDIM 2048
#define HID 20
#define NBLK 32
#define PIT 40   // SMEM row pitch in halves (80B rows, 16B-aligned, ldmatrix conflict-free)

// ---------------- fp32 scratch ----------------
__device__ float g_G   [(size_t)RDIM * CDIM];
__device__ float g_P0  [(size_t)RDIM * CDIM];
__device__ float g_B   [(size_t)RDIM * CDIM];
__device__ float g_A   [(size_t)CDIM * CDIM];
__device__ float g_Gram[(size_t)CDIM * CDIM];
__device__ float g_Rinv[(size_t)CDIM * CDIM];
__device__ float g_T   [(size_t)1024 * 1024];
__device__ float g_rowp[16 * (size_t)RDIM];
__device__ float g_dL[RDIM];
__device__ float g_dR[CDIM];
__device__ float g_lraw[RDIM];
__device__ float g_rraw[CDIM];
__device__ float g_partL[32];
__device__ float g_partR[8];
__device__ float g_means[2];
__device__ float g_Lv[RDIM];
__device__ float g_Rv[CDIM];

// ---------------- bf16 split scratch ----------------
__device__ __align__(16) __nv_bfloat16 g_sH  [(size_t)RDIM * CDIM];
__device__ __align__(16) __nv_bfloat16 g_sL  [(size_t)RDIM * CDIM];
__device__ __align__(16) __nv_bfloat16 g_sTh [(size_t)RDIM * CDIM];
__device__ __align__(16) __nv_bfloat16 g_sTl [(size_t)RDIM * CDIM];
__device__ __align__(16) __nv_bfloat16 g_sgH [(size_t)RDIM * CDIM];
__device__ __align__(16) __nv_bfloat16 g_sgL [(size_t)RDIM * CDIM];
__device__ __align__(16) __nv_bfloat16 g_P0h [(size_t)RDIM * CDIM];
__device__ __align__(16) __nv_bfloat16 g_P0l [(size_t)RDIM * CDIM];
__device__ __align__(16) __nv_bfloat16 g_BH  [(size_t)RDIM * CDIM];
__device__ __align__(16) __nv_bfloat16 g_BL  [(size_t)RDIM * CDIM];
__device__ __align__(16) __nv_bfloat16 g_BTh [(size_t)RDIM * CDIM];
__device__ __align__(16) __nv_bfloat16 g_BTl [(size_t)RDIM * CDIM];
__device__ __align__(16) __nv_bfloat16 g_AsH [(size_t)CDIM * CDIM];
__device__ __align__(16) __nv_bfloat16 g_AsL [(size_t)CDIM * CDIM];
__device__ __align__(16) __nv_bfloat16 g_RiH [(size_t)CDIM * CDIM];
__device__ __align__(16) __nv_bfloat16 g_RiL [(size_t)CDIM * CDIM];

// ---------------- helpers ----------------
__device__ __forceinline__ void mma_bf16(float* c, const unsigned* a, const unsigned* b) {
    asm volatile(
        "mma.sync.aligned.m16n8k16.row.col.f32.bf16.bf16.f32 "
        "{%0,%1,%2,%3},{%4,%5,%6,%7},{%8,%9},{%0,%1,%2,%3};"
        : "+f"(c[0]), "+f"(c[1]), "+f"(c[2]), "+f"(c[3])
        : "r"(a[0]), "r"(a[1]), "r"(a[2]), "r"(a[3]), "r"(b[0]), "r"(b[1]));
}
__device__ __forceinline__ unsigned s2u(const void* p) {
    return (unsigned)__cvta_generic_to_shared(p);
}
__device__ __forceinline__ void ldsm4(unsigned* d, unsigned a) {
    asm volatile("ldmatrix.sync.aligned.m8n8.x4.shared.b16 {%0,%1,%2,%3},[%4];"
        : "=r"(d[0]), "=r"(d[1]), "=r"(d[2]), "=r"(d[3]) : "r"(a));
}
__device__ __forceinline__ void ldsm2(unsigned* d, unsigned a) {
    asm volatile("ldmatrix.sync.aligned.m8n8.x2.shared.b16 {%0,%1},[%2];"
        : "=r"(d[0]), "=r"(d[1]) : "r"(a));
}
__device__ __forceinline__ void cpa16(unsigned d, const void* gp) {
    asm volatile("cp.async.cg.shared.global [%0], [%1], 16;" :: "r"(d), "l"(gp) : "memory");
}
__device__ __forceinline__ void cpcommit() { asm volatile("cp.async.commit_group;" ::: "memory"); }
__device__ __forceinline__ void cpwait1()  { asm volatile("cp.async.wait_group 1;" ::: "memory"); }
__device__ __forceinline__ void cpwait0()  { asm volatile("cp.async.wait_group 0;" ::: "memory"); }

__device__ __forceinline__ void bfsplit(float v, __nv_bfloat16& h, __nv_bfloat16& l) {
    h = __float2bfloat16(v);
    l = __float2bfloat16(v - __bfloat162float(h));
}

// consume one 128x128x32 staged tile: 2 k16 chunks, ldmatrix + 3-pass split MMA
__device__ __forceinline__ void consume_tile(
    const __nv_bfloat16* Ah, const __nv_bfloat16* Al,
    const __nv_bfloat16* Bh, const __nv_bfloat16* Bl,
    int wm, int wn, int lane, float acc[4][4][4])
{
    int ar = lane & 15, ac = (lane >> 4) * 8;
    int br = lane & 7,  bc = ((lane >> 3) & 1) * 8;
#pragma unroll
    for (int ch = 0; ch < 2; ch++) {
        int ck = ch * 16;
        unsigned afh[4][4], afl[4][4], bfh[4][2], bfl[4][2];
#pragma unroll
        for (int mi = 0; mi < 4; mi++) {
            ldsm4(afh[mi], s2u(&Ah[(wm + mi * 16 + ar) * PIT + ck + ac]));
            ldsm4(afl[mi], s2u(&Al[(wm + mi * 16 + ar) * PIT + ck + ac]));
        }
#pragma unroll
        for (int ni = 0; ni < 4; ni++) {
            ldsm2(bfh[ni], s2u(&Bh[(wn + ni * 8 + br) * PIT + ck + bc]));
            ldsm2(bfl[ni], s2u(&Bl[(wn + ni * 8 + br) * PIT + ck + bc]));
        }
#pragma unroll
        for (int mi = 0; mi < 4; mi++)
#pragma unroll
            for (int ni = 0; ni < 4; ni++) {
                mma_bf16(acc[mi][ni], afh[mi], bfh[ni]);
                mma_bf16(acc[mi][ni], afh[mi], bfl[ni]);
                mma_bf16(acc[mi][ni], afl[mi], bfh[ni]);
            }
    }
}

// ---------------- unified split-bf16 tensor GEMM ----------------
// C[p,q] = gamma * sum_k (Ah+Al)[k + p*ldA] * (Bh+Bl)[k + q*ldB]   (+ alpha*X + beta*Y)
// optional bf16 split outputs Ch/Cl. flags: 1 = upper blocks only, 2 = triK (k < q0+128)
__global__ __launch_bounds__(256) void tgemm(
    const __nv_bfloat16* __restrict__ Ahg, const __nv_bfloat16* __restrict__ Alg, int ldA,
    const __nv_bfloat16* __restrict__ Bhg, const __nv_bfloat16* __restrict__ Blg, int ldB,
    const float* __restrict__ X, float alpha, const float* __restrict__ Y, float beta,
    float gamma, float* __restrict__ Cout,
    __nv_bfloat16* __restrict__ Ch, __nv_bfloat16* __restrict__ Cl, int ldc,
    int K, int flags)
{
    extern __shared__ __nv_bfloat16 smb[];
    int p0 = blockIdx.x * 128, q0 = blockIdx.y * 128;
    if ((flags & 1) && q0 < p0) return;
    int kmax = (flags & 2) ? (q0 + 128 < K ? q0 + 128 : K) : K;

    int tid = threadIdx.x, lane = tid & 31, warp = tid >> 5;
    int wm = (warp >> 2) * 64, wn = (warp & 3) * 32;
    int g = lane >> 2, tg = lane & 3;
    float acc[4][4][4];
#pragma unroll
    for (int i = 0; i < 4; i++)
#pragma unroll
        for (int j = 0; j < 4; j++)
#pragma unroll
            for (int k = 0; k < 4; k++) acc[i][j][k] = 0.f;

    int row = tid >> 1, kh = (tid & 1) * 16;
    const __nv_bfloat16* pAh = Ahg + (size_t)(p0 + row) * ldA + kh;
    const __nv_bfloat16* pAl = Alg + (size_t)(p0 + row) * ldA + kh;
    const __nv_bfloat16* pBh = Bhg + (size_t)(q0 + row) * ldB + kh;
    const __nv_bfloat16* pBl = Blg + (size_t)(q0 + row) * ldB + kh;
    unsigned dst0 = s2u(smb) + (unsigned)(row * PIT + kh) * 2;

#define STAGE(buf, k0) { unsigned d = dst0 + (buf) * 40960u; \
    cpa16(d,         pAh + (k0)); cpa16(d + 16,    pAh + (k0) + 8); \
    cpa16(d + 10240, pAl + (k0)); cpa16(d + 10256, pAl + (k0) + 8); \
    cpa16(d + 20480, pBh + (k0)); cpa16(d + 20496, pBh + (k0) + 8); \
    cpa16(d + 30720, pBl + (k0)); cpa16(d + 30736, pBl + (k0) + 8); \
    cpcommit(); }

    int niter = kmax / 32;
    STAGE(0, 0)
    for (int i = 0; i < niter; i++) {
        if (i + 1 < niter) { STAGE((i + 1) & 1, (i + 1) * 32) cpwait1(); }
        else cpwait0();
        __syncthreads();
        const __nv_bfloat16* base = smb + (i & 1) * 20480;
        consume_tile(base, base + 5120, base + 10240, base + 15360, wm, wn, lane, acc);
        __syncthreads();
    }
#undef STAGE

#pragma unroll
    for (int mi = 0; mi < 4; mi++)
#pragma unroll
        for (int ni = 0; ni < 4; ni++) {
            int p = p0 + wm + mi * 16 + g;
            int q = q0 + wn + ni * 8 + 2 * tg;
            float* c = acc[mi][ni];
            size_t o00 = (size_t)q * ldc + p;
            size_t o01 = (size_t)(q + 1) * ldc + p;
            float v00 = gamma * c[0], v01 = gamma * c[1];
            float v10 = gamma * c[2], v11 = gamma * c[3];
            if (X) { v00 += alpha * X[o00]; v01 += alpha * X[o01]; v10 += alpha * X[o00 + 8]; v11 += alpha * X[o01 + 8]; }
            if (Y) { v00 += beta * Y[o00]; v01 += beta * Y[o01]; v10 += beta * Y[o00 + 8]; v11 += beta * Y[o01 + 8]; }
            Cout[o00] = v00; Cout[o01] = v01; Cout[o00 + 8] = v10; Cout[o01 + 8] = v11;
            if (Ch) {
                __nv_bfloat16 h, l;
                bfsplit(v00, h, l); Ch[o00] = h; Cl[o00] = l;
                bfsplit(v01, h, l); Ch[o01] = h; Cl[o01] = l;
                bfsplit(v10, h, l); Ch[o00 + 8] = h; Cl[o00 + 8] = l;
                bfsplit(v11, h, l); Ch[o01 + 8] = h; Cl[o01 + 8] = l;
            }
        }
}

// ---------------- split / transpose-split kernels ----------------
__global__ void splitK(const float* __restrict__ x,
                       __nv_bfloat16* __restrict__ oh, __nv_bfloat16* __restrict__ ol) {
    size_t i = (size_t)blockIdx.x * 256 + threadIdx.x;
    __nv_bfloat16 h, l;
    bfsplit(x[i], h, l);
    oh[i] = h; ol[i] = l;
}

// X: 8192x2048 col-major (m-leading) -> XT[p*2048 + k] split
__global__ void tspK(const float* __restrict__ X,
                     __nv_bfloat16* __restrict__ oh, __nv_bfloat16* __restrict__ ol) {
    __shared__ float t[32][33];
    int p0 = blockIdx.x * 32, k0 = blockIdx.y * 32;
    int tx = threadIdx.x, ty = threadIdx.y;
#pragma unroll
    for (int j = 0; j < 32; j += 8)
        t[ty + j][tx] = X[(size_t)(k0 + ty + j) * RDIM + p0 + tx];
    __syncthreads();
#pragma unroll
    for (int j = 0; j < 32; j += 8) {
        float v = t[tx][ty + j];
        size_t o = (size_t)(p0 + ty + j) * CDIM + k0 + tx;
        __nv_bfloat16 h, l; bfsplit(v, h, l);
        oh[o] = h; ol[o] = l;
    }
}

__global__ void symSplitK(const float* __restrict__ in,
                          __nv_bfloat16* __restrict__ oh, __nv_bfloat16* __restrict__ ol) {
    int idx = blockIdx.x * 256 + threadIdx.x;
    int p = idx & (CDIM - 1), q = idx >> 11;
    float v = 0.5f * (in[idx] + in[(size_t)p * CDIM + q]);
    __nv_bfloat16 h, l; bfsplit(v, h, l);
    oh[idx] = h; ol[idx] = l;
}

// ---------------- FFMA GEMM (A^T x B) for Cholesky trailing updates ----------------
__global__ __launch_bounds__(256) void gemm_tn(
    const float* __restrict__ A, int lda, const float* __restrict__ B, int ldb,
    const float* __restrict__ Cin, float* __restrict__ Cout, int ldc,
    int K, float alpha, int upperOnly)
{
    int p0 = blockIdx.x * 64, q0 = blockIdx.y * 64;
    if (upperOnly && q0 < p0) return;
    __shared__ float As[16][68];
    __shared__ float Bs[16][68];
    int tid = threadIdx.x, tx = tid & 15, ty = tid >> 4;
    float acc[4][4];
#pragma unroll
    for (int a = 0; a < 4; a++)
#pragma unroll
        for (int b = 0; b < 4; b++) acc[a][b] = 0.f;
    for (int k0 = 0; k0 < K; k0 += 16) {
#pragma unroll
        for (int s2 = 0; s2 < 4; s2++) {
            int idx = tid + s2 * 256;
            int kk = idx & 15, pp = idx >> 4;
            As[kk][pp] = A[(size_t)(p0 + pp) * lda + (k0 + kk)];
            Bs[kk][pp] = B[(size_t)(q0 + pp) * ldb + (k0 + kk)];
        }
        __syncthreads();
#pragma unroll
        for (int kk = 0; kk < 16; kk++) {
            float4 av = *(const float4*)&As[kk][ty * 4];
            float4 bv = *(const float4*)&Bs[kk][tx * 4];
            float ar[4] = {av.x, av.y, av.z, av.w};
            float br[4] = {bv.x, bv.y, bv.z, bv.w};
#pragma unroll
            for (int a = 0; a < 4; a++)
#pragma unroll
                for (int b = 0; b < 4; b++)
                    acc[a][b] = fmaf(ar[a], br[b], acc[a][b]);
        }
        __syncthreads();
    }
#pragma unroll
    for (int a = 0; a < 4; a++)
#pragma unroll
        for (int b = 0; b < 4; b++) {
            int p = p0 + ty * 4 + a, q = q0 + tx * 4 + b;
            size_t o = (size_t)q * ldc + p;
            float v = alpha * acc[a][b];
            if (Cin) v += Cin[o];
            Cout[o] = v;
        }
}

// ---------------- batched FFMA NN GEMM for recursive triangular inverse ----------------
__global__ __launch_bounds__(256) void gemm_nn_b(
    const float* __restrict__ A, long long sA, int lda,
    const float* __restrict__ B, long long sB, int ldb,
    float* __restrict__ C, long long sC, int ldc, int K, float sgn)
{
    const float* Ap = A + (size_t)blockIdx.z * sA;
    const float* Bp = B + (size_t)blockIdx.z * sB;
    float* Cp = C + (size_t)blockIdx.z * sC;
    int i0 = blockIdx.x * 64, q0 = blockIdx.y * 64;
    __shared__ float As[16][68];
    __shared__ float Bs[16][68];
    int tid = threadIdx.x, tx = tid & 15, ty = tid >> 4;
    float acc[4][4];
#pragma unroll
    for (int a = 0; a < 4; a++)
#pragma unroll
        for (int b = 0; b < 4; b++) acc[a][b] = 0.f;
    for (int k0 = 0; k0 < K; k0 += 16) {
#pragma unroll
        for (int s2 = 0; s2 < 4; s2++) {
            int idx = tid + s2 * 256;
            int ii = idx & 63, kk = idx >> 6;
            As[kk][ii] = Ap[(size_t)(k0 + kk) * lda + (i0 + ii)];
            int kk2 = idx & 15, qq = idx >> 4;
            Bs[kk2][qq] = Bp[(size_t)(q0 + qq) * ldb + (k0 + kk2)];
        }
        __syncthreads();
#pragma unroll
        for (int kk = 0; kk < 16; kk++) {
            float4 av = *(const float4*)&As[kk][ty * 4];
            float4 bv = *(const float4*)&Bs[kk][tx * 4];
            float ar[4] = {av.x, av.y, av.z, av.w};
            float br[4] = {bv.x, bv.y, bv.z, bv.w};
#pragma unroll
            for (int a = 0; a < 4; a++)
#pragma unroll
                for (int b = 0; b < 4; b++)
                    acc[a][b] = fmaf(ar[a], br[b], acc[a][b]);
        }
        __syncthreads();
    }
#pragma unroll
    for (int a = 0; a < 4; a++)
#pragma unroll
        for (int b = 0; b < 4; b++) {
            int p = i0 + ty * 4 + a, q = q0 + tx * 4 + b;
            Cp[(size_t)q * ldc + p] = sgn * acc[a][b];
        }
}

// ---------------- small kernels ----------------
__global__ void zeroBufK(float* p) { p[(size_t)blockIdx.x * 256 + threadIdx.x] = 0.f; }

__global__ void rowsqK() {
    int i = blockIdx.x * 256 + threadIdx.x;
    int q0 = blockIdx.y * (CDIM / 16);
    float acc = 0.f;
    for (int q = q0; q < q0 + CDIM / 16; q++) {
        float v = g_G[(size_t)q * RDIM + i];
        acc += v * v;
    }
    g_rowp[(size_t)blockIdx.y * RDIM + i] = acc;
}
__global__ void rowcombK() {
    int i = blockIdx.x * 256 + threadIdx.x;
    float s = 0.f;
    for (int ch = 0; ch < 16; ch++) s += g_rowp[(size_t)ch * RDIM + i];
    g_dL[i] = s / (float)CDIM;
}
__global__ void colsqK() {
    __shared__ float red[256];
    int q = blockIdx.x, tid = threadIdx.x;
    const float* col = g_G + (size_t)q * RDIM;
    float acc = 0.f;
    for (int i = tid; i < RDIM; i += 256) { float v = col[i]; acc += v * v; }
    red[tid] = acc; __syncthreads();
    for (int s = 128; s > 0; s >>= 1) { if (tid < s) red[tid] += red[tid + s]; __syncthreads(); }
    if (tid == 0) g_dR[q] = red[0] / (float)RDIM;
}

__device__ __forceinline__ float sigm(float x) { return 1.f / (1.f + expf(-x)); }

__global__ __launch_bounds__(256) void lstmK(
    int N, const float* __restrict__ diag,
    const float* __restrict__ h0, const float* __restrict__ c0,
    const float* __restrict__ Wih0, const float* __restrict__ Whh0,
    const float* __restrict__ bih0, const float* __restrict__ bhh0,
    const float* __restrict__ Wih1, const float* __restrict__ Whh1,
    const float* __restrict__ bih1, const float* __restrict__ bhh1,
    const float* __restrict__ LW, const float* __restrict__ Lb,
    float* __restrict__ raw, float* __restrict__ part)
{
    __shared__ float sWih0[80], sB0[80], sB1[80];
    __shared__ float sWhh0[1600], sWih1[1600], sWhh1[1600];
    __shared__ float sLW[HID];
    int tid = threadIdx.x;
    for (int k = tid; k < 80; k += 256) {
        sWih0[k] = Wih0[k];
        sB0[k] = bih0[k] + bhh0[k];
        sB1[k] = bih1[k] + bhh1[k];
    }
    for (int k = tid; k < 1600; k += 256) {
        sWhh0[k] = Whh0[k]; sWih1[k] = Wih1[k]; sWhh1[k] = Whh1[k];
    }
    if (tid < HID) sLW[tid] = LW[tid];
    __syncthreads();

    int n = blockIdx.x * 256 + tid;
    float d = diag[n];
    float x = logf(fabsf(d)) * 0.1f;
    x = fminf(fmaxf(x, -1.f), 1.f);

    float hp[HID], h1[HID];
    const float* h0p = h0 + (size_t)n * HID;
    const float* c0p = c0 + (size_t)n * HID;
#pragma unroll
    for (int j = 0; j < HID; j++) hp[j] = h0p[j];
    for (int jh = 0; jh < HID; jh++) {
        float gi = sB0[jh]      + sWih0[jh] * x;
        float gf = sB0[20 + jh] + sWih0[20 + jh] * x;
        float gg = sB0[40 + jh] + sWih0[40 + jh] * x;
        float go = sB0[60 + jh] + sWih0[60 + jh] * x;
#pragma unroll
        for (int j = 0; j < HID; j++) {
            float hv = hp[j];
            gi = fmaf(sWhh0[jh * 20 + j], hv, gi);
            gf = fmaf(sWhh0[(20 + jh) * 20 + j], hv, gf);
            gg = fmaf(sWhh0[(40 + jh) * 20 + j], hv, gg);
            go = fmaf(sWhh0[(60 + jh) * 20 + j], hv, go);
        }
        float cc = sigm(gf) * c0p[jh] + sigm(gi) * tanhf(gg);
        h1[jh] = sigm(go) * tanhf(cc);
    }
    const float* h1p = h0 + (size_t)N * HID + (size_t)n * HID;
    const float* c1p = c0 + (size_t)N * HID + (size_t)n * HID;
    float hb[HID];
#pragma unroll
    for (int j = 0; j < HID; j++) hb[j] = h1p[j];
    float o = 0.f;
    for (int jh = 0; jh < HID; jh++) {
        float gi = sB1[jh], gf = sB1[20 + jh], gg = sB1[40 + jh], go = sB1[60 + jh];
#pragma unroll
        for (int j = 0; j < HID; j++) {
            float a = h1[j], b = hb[j];
            gi = fmaf(sWih1[jh * 20 + j], a, fmaf(sWhh1[jh * 20 + j], b, gi));
            gf = fmaf(sWih1[(20 + jh) * 20 + j], a, fmaf(sWhh1[(20 + jh) * 20 + j], b, gf));
            gg = fmaf(sWih1[(40 + jh) * 20 + j], a, fmaf(sWhh1[(40 + jh) * 20 + j], b, gg));
            go = fmaf(sWih1[(60 + jh) * 20 + j], a, fmaf(sWhh1[(60 + jh) * 20 + j], b, go));
        }
        float cc = sigm(gf) * c1p[jh] + sigm(gi) * tanhf(gg);
        float h2 = sigm(go) * tanhf(cc);
        o = fmaf(sLW[jh], h2, o);
    }
    float val = (o + Lb[0]) * 0.1f;
    raw[n] = val;

    __shared__ float red[256];
    red[tid] = val; __syncthreads();
    for (int s = 128; s > 0; s >>= 1) { if (tid < s) red[tid] += red[tid + s]; __syncthreads(); }
    if (tid == 0) part[blockIdx.x] = red[0];
}

__global__ void meansK() {
    if (threadIdx.x == 0) {
        float s = 0.f; for (int i = 0; i < 32; i++) s += g_partL[i];
        g_means[0] = s / (float)RDIM;
        float t = 0.f; for (int i = 0; i < 8; i++) t += g_partR[i];
        g_means[1] = t / (float)CDIM;
    }
}

__global__ void applyK(const float* __restrict__ raw, const float* __restrict__ before,
                       int mi, float* __restrict__ outv) {
    int i = blockIdx.x * 256 + threadIdx.x;
    outv[i] = fmaxf(raw[i] - g_means[mi] + 1.0f, before[i]);
}

__global__ void p0K() {
    size_t idx = (size_t)blockIdx.x * 256 + threadIdx.x;
    int i = (int)(idx & (RDIM - 1));
    int q = (int)(idx >> 13);
    float v = g_Lv[i] * g_G[idx] * g_Rv[q];
    g_P0[idx] = v;
    __nv_bfloat16 h, l; bfsplit(v, h, l);
    g_P0h[idx] = h; g_P0l[idx] = l;
}

// ---------------- Cholesky ----------------
__global__ void cholDiagK(int k0) {
    __shared__ float S[64][65];
    int t = threadIdx.x;
    for (int e = t; e < 4096; e += 64) {
        int a = e & 63, b = e >> 6;
        S[a][b] = g_Gram[(size_t)(k0 + b) * CDIM + (k0 + a)];
    }
    __syncthreads();
    for (int j = 0; j < 64; j++) {
        if (t == 0) S[j][j] = sqrtf(S[j][j]);
        __syncthreads();
        float rjj = S[j][j];
        if (t > j) S[j][t] /= rjj;
        __syncthreads();
        if (t > j) {
            float sjt = S[j][t];
            for (int a = j + 1; a <= t; a++) S[a][t] -= S[j][a] * sjt;
        }
        __syncthreads();
    }
    for (int e = t; e < 4096; e += 64) {
        int a = e & 63, b = e >> 6;
        if (a <= b) g_Gram[(size_t)(k0 + b) * CDIM + (k0 + a)] = S[a][b];
    }
}

__global__ void cholTrsmK(int k0) {
    __shared__ float Rkk[64][65];
    __shared__ float Xs[64][65];
    int t = threadIdx.x;
    int qb = k0 + 64 + blockIdx.x * 64;
    for (int e = t; e < 4096; e += 64) {
        int a = e & 63, b = e >> 6;
        Rkk[a][b] = g_Gram[(size_t)(k0 + b) * CDIM + (k0 + a)];
        Xs[a][b]  = g_Gram[(size_t)(qb + b) * CDIM + (k0 + a)];
    }
    __syncthreads();
    for (int a = 0; a < 64; a++) {
        float sum = 0.f;
        for (int b = 0; b < a; b++) sum = fmaf(Rkk[b][a], Xs[b][t], sum);
        Xs[a][t] = (Xs[a][t] - sum) / Rkk[a][a];
    }
    __syncthreads();
    for (int e = t; e < 4096; e += 64) {
        int a = e & 63, b = e >> 6;
        g_Gram[(size_t)(qb + b) * CDIM + (k0 + a)] = Xs[a][b];
    }
}

__global__ void invDiagK() {
    int k0 = blockIdx.x * 64;
    __shared__ float U[64][65];
    __shared__ float Xs[64][65];
    int t = threadIdx.x;
    for (int e = t; e < 4096; e += 64) {
        int a = e & 63, b = e >> 6;
        U[a][b] = (a <= b) ? g_Gram[(size_t)(k0 + b) * CDIM + (k0 + a)] : 0.f;
        Xs[a][b] = 0.f;
    }
    __syncthreads();
    for (int a = 63; a >= 0; a--) {
        if (a <= t) {
            float sum = (a == t) ? 1.f : 0.f;
            for (int b = a + 1; b <= t; b++) sum = fmaf(-U[a][b], Xs[b][t], sum);
            Xs[a][t] = sum / U[a][a];
        }
    }
    __syncthreads();
    for (int e = t; e < 4096; e += 64) {
        int a = e & 63, b = e >> 6;
        g_Rinv[(size_t)(k0 + b) * CDIM + (k0 + a)] = Xs[a][b];
    }
}

extern "C" void kernel_launch(void* const* d_in, const int* in_sizes, int n_in,
                              void* d_out, int out_size) {
    const float* s   = (const float*)d_in[0];
    const float* sg  = (const float*)d_in[1];
    const float* Lh0 = (const float*)d_in[2];
    const float* Lc0 = (const float*)d_in[3];
    const float* Rh0 = (const float*)d_in[4];
    const float* Rc0 = (const float*)d_in[5];
    const float* Lbef = (const float*)d_in[6];
    const float* Rbef = (const float*)d_in[7];
    const float* Wih0 = (const float*)d_in[8];
    const float* Whh0 = (const float*)d_in[9];
    const float* bih0 = (const float*)d_in[10];
    const float* bhh0 = (const float*)d_in[11];
    const float* Wih1 = (const float*)d_in[12];
    const float* Whh1 = (const float*)d_in[13];
    const float* bih1 = (const float*)d_in[14];
    const float* bhh1 = (const float*)d_in[15];
    const float* LW = (const float*)d_in[16];
    const float* Lb = (const float*)d_in[17];
    const float* RW = (const float*)d_in[18];
    const float* Rb = (const float*)d_in[19];
    float* out = (float*)d_out;

    float *gG, *gP0, *gB, *gA, *gGram, *gRinv, *gT;
    float *gdL, *gdR, *glraw, *grraw, *gpartL, *gpartR, *gLv, *gRv;
    __nv_bfloat16 *sH, *sL, *sTh, *sTl, *sgH, *sgL, *P0h, *P0l;
    __nv_bfloat16 *BH, *BL, *BTh, *BTl, *AsH, *AsL, *RiH, *RiL;
    cudaGetSymbolAddress((void**)&gG, g_G);
    cudaGetSymbolAddress((void**)&gP0, g_P0);
    cudaGetSymbolAddress((void**)&gB, g_B);
    cudaGetSymbolAddress((void**)&gA, g_A);
    cudaGetSymbolAddress((void**)&gGram, g_Gram);
    cudaGetSymbolAddress((void**)&gRinv, g_Rinv);
    cudaGetSymbolAddress((void**)&gT, g_T);
    cudaGetSymbolAddress((void**)&gdL, g_dL);
    cudaGetSymbolAddress((void**)&gdR, g_dR);
    cudaGetSymbolAddress((void**)&glraw, g_lraw);
    cudaGetSymbolAddress((void**)&grraw, g_rraw);
    cudaGetSymbolAddress((void**)&gpartL, g_partL);
    cudaGetSymbolAddress((void**)&gpartR, g_partR);
    cudaGetSymbolAddress((void**)&gLv, g_Lv);
    cudaGetSymbolAddress((void**)&gRv, g_Rv);
    cudaGetSymbolAddress((void**)&sH, g_sH);
    cudaGetSymbolAddress((void**)&sL, g_sL);
    cudaGetSymbolAddress((void**)&sTh, g_sTh);
    cudaGetSymbolAddress((void**)&sTl, g_sTl);
    cudaGetSymbolAddress((void**)&sgH, g_sgH);
    cudaGetSymbolAddress((void**)&sgL, g_sgL);
    cudaGetSymbolAddress((void**)&P0h, g_P0h);
    cudaGetSymbolAddress((void**)&P0l, g_P0l);
    cudaGetSymbolAddress((void**)&BH, g_BH);
    cudaGetSymbolAddress((void**)&BL, g_BL);
    cudaGetSymbolAddress((void**)&BTh, g_BTh);
    cudaGetSymbolAddress((void**)&BTl, g_BTl);
    cudaGetSymbolAddress((void**)&AsH, g_AsH);
    cudaGetSymbolAddress((void**)&AsL, g_AsL);
    cudaGetSymbolAddress((void**)&RiH, g_RiH);
    cudaGetSymbolAddress((void**)&RiL, g_RiL);

    cudaFuncSetAttribute(tgemm, cudaFuncAttributeMaxDynamicSharedMemorySize, 81920);
    const int NELEM = RDIM * CDIM / 256;

    // 1-3: operand splits
    splitK<<<NELEM, 256>>>(s, sH, sL);
    splitK<<<NELEM, 256>>>(sg, sgH, sgL);
    tspK<<<dim3(RDIM / 32, CDIM / 32), dim3(32, 8)>>>(s, sTh, sTl);
    // 4 (profiled): A = 0.1 * s^T sg
    tgemm<<<dim3(16, 16), 256, 81920>>>(sH, sL, RDIM, sgH, sgL, RDIM,
        nullptr, 0.f, nullptr, 0.f, 0.1f, gA, nullptr, nullptr, CDIM, RDIM, 0);
    symSplitK<<<CDIM * CDIM / 256, 256>>>(gA, AsH, AsL);
    // G = 0.1*sg - s*As
    tgemm<<<dim3(64, 16), 256, 81920>>>(sTh, sTl, CDIM, AsH, AsL, CDIM,
        sg, 0.1f, nullptr, 0.f, -1.f, gG, nullptr, nullptr, RDIM, CDIM, 0);
    // Gram diagonals
    rowsqK<<<dim3(32, 16), 256>>>();
    rowcombK<<<32, 256>>>();
    colsqK<<<CDIM, 256>>>();
    // LSTMs
    lstmK<<<32, 256>>>(RDIM, gdL, Lh0, Lc0, Wih0, Whh0, bih0, bhh0, Wih1, Whh1, bih1, bhh1, LW, Lb, glraw, gpartL);
    lstmK<<<8, 256>>>(CDIM, gdR, Rh0, Rc0, Wih0, Whh0, bih0, bhh0, Wih1, Whh1, bih1, bhh1, RW, Rb, grraw, gpartR);
    meansK<<<1, 32>>>();
    applyK<<<32, 256>>>(glraw, Lbef, 0, gLv);
    applyK<<<8, 256>>>(grraw, Rbef, 1, gRv);
    // P0 = Lv . G . Rv (fp32 + split)
    p0K<<<NELEM, 256>>>();
    // A2 = s^T P0 ; As2 ; B = s*As2 + s - P0 (fp32 + split)
    tgemm<<<dim3(16, 16), 256, 81920>>>(sH, sL, RDIM, P0h, P0l, RDIM,
        nullptr, 0.f, nullptr, 0.f, 1.f, gA, nullptr, nullptr, CDIM, RDIM, 0);
    symSplitK<<<CDIM * CDIM / 256, 256>>>(gA, AsH, AsL);
    tgemm<<<dim3(64, 16), 256, 81920>>>(sTh, sTl, CDIM, AsH, AsL, CDIM,
        s, 1.f, gP0, -1.f, 1.f, gB, BH, BL, RDIM, CDIM, 0);
    tspK<<<dim3(RDIM / 32, CDIM / 32), dim3(32, 8)>>>(gB, BTh, BTl);
    // Gram = B^T B (upper)
    tgemm<<<dim3(16, 16), 256, 81920>>>(BH, BL, RDIM, BH, BL, RDIM,
        nullptr, 0.f, nullptr, 0.f, 1.f, gGram, nullptr, nullptr, CDIM, RDIM, 1);
    // blocked Cholesky
    for (int k = 0; k < NBLK; k++) {
        cholDiagK<<<1, 64>>>(k * 64);
        int nb = NBLK - 1 - k;
        if (nb > 0) {
            cholTrsmK<<<nb, 64>>>(k * 64);
            int r0 = (k + 1) * 64;
            const float* panel = gGram + (size_t)r0 * CDIM + k * 64;
            float* base = gGram + (size_t)r0 * CDIM + r0;
            gemm_tn<<<dim3(nb, nb), 256>>>(panel, CDIM, panel, CDIM, base, base, CDIM, 64, -1.f, 1);
        }
    }
    // Rinv via recursive doubling
    zeroBufK<<<CDIM * CDIM / 256, 256>>>(gRinv);
    invDiagK<<<NBLK, 64>>>();
    for (int b = 64; b <= 1024; b *= 2) {
        int npairs = CDIM / (2 * b);
        dim3 g1(b / 64, b / 64, npairs);
        long long strideP = (long long)2 * b * (CDIM + 1);
        gemm_nn_b<<<g1, 256>>>(gGram + (size_t)b * CDIM, strideP, CDIM,
                               gRinv + (size_t)b * CDIM + b, strideP, CDIM,
                               gT, (long long)b * b, b, b, 1.f);
        gemm_nn_b<<<g1, 256>>>(gRinv, strideP, CDIM,
                               gT, (long long)b * b, b,
                               gRinv + (size_t)b * CDIM, strideP, CDIM, b, -1.f);
    }
    splitK<<<CDIM * CDIM / 256, 256>>>(gRinv, RiH, RiL);
    // Q = B * Rinv -> out
    tgemm<<<dim3(64, 16), 256, 81920>>>(BTh, BTl, CDIM, RiH, RiL, CDIM,
        nullptr, 0.f, nullptr, 0.f, 1.f, out, nullptr, nullptr, RDIM, CDIM, 2);
}

// round 14
// speedup vs baseline: 1.2951x; 1.1875x over previous
#include <cuda_runtime.h>
#include <cuda_bf16.h>
#include <math.h>
#include <stdint.h>

#define RDIM 8192
#define CDIM 2048
#define HID 20
#define NBLK 32
#define PIT 40   // SMEM row pitch in halves (80B rows, 16B-aligned, ldmatrix conflict-free)

// ---------------- fp32 scratch ----------------
__device__ float g_G   [(size_t)RDIM * CDIM];
__device__ float g_P0  [(size_t)RDIM * CDIM];
__device__ float g_B   [(size_t)RDIM * CDIM];
__device__ float g_A   [(size_t)CDIM * CDIM];
__device__ float g_Gram[(size_t)CDIM * CDIM];
__device__ float g_Rinv[(size_t)CDIM * CDIM];
__device__ float g_T   [(size_t)1024 * 1024];
__device__ float g_rowp[16 * (size_t)RDIM];
__device__ float g_dL[RDIM];
__device__ float g_dR[CDIM];
__device__ float g_lraw[RDIM];
__device__ float g_rraw[CDIM];
__device__ float g_partL[32];
__device__ float g_partR[8];
__device__ float g_means[2];
__device__ float g_Lv[RDIM];
__device__ float g_Rv[CDIM];

// ---------------- bf16 split scratch ----------------
__device__ __align__(16) __nv_bfloat16 g_sH  [(size_t)RDIM * CDIM];
__device__ __align__(16) __nv_bfloat16 g_sL  [(size_t)RDIM * CDIM];
__device__ __align__(16) __nv_bfloat16 g_sTh [(size_t)RDIM * CDIM];
__device__ __align__(16) __nv_bfloat16 g_sTl [(size_t)RDIM * CDIM];
__device__ __align__(16) __nv_bfloat16 g_sgH [(size_t)RDIM * CDIM];
__device__ __align__(16) __nv_bfloat16 g_sgL [(size_t)RDIM * CDIM];
__device__ __align__(16) __nv_bfloat16 g_P0h [(size_t)RDIM * CDIM];
__device__ __align__(16) __nv_bfloat16 g_P0l [(size_t)RDIM * CDIM];
__device__ __align__(16) __nv_bfloat16 g_BH  [(size_t)RDIM * CDIM];
__device__ __align__(16) __nv_bfloat16 g_BL  [(size_t)RDIM * CDIM];
__device__ __align__(16) __nv_bfloat16 g_BTh [(size_t)RDIM * CDIM];
__device__ __align__(16) __nv_bfloat16 g_BTl [(size_t)RDIM * CDIM];
__device__ __align__(16) __nv_bfloat16 g_AsH [(size_t)CDIM * CDIM];
__device__ __align__(16) __nv_bfloat16 g_AsL [(size_t)CDIM * CDIM];
__device__ __align__(16) __nv_bfloat16 g_RiH [(size_t)CDIM * CDIM];
__device__ __align__(16) __nv_bfloat16 g_RiL [(size_t)CDIM * CDIM];

// ---------------- helpers ----------------
__device__ __forceinline__ void mma_bf16(float* c, const unsigned* a, const unsigned* b) {
    asm volatile(
        "mma.sync.aligned.m16n8k16.row.col.f32.bf16.bf16.f32 "
        "{%0,%1,%2,%3},{%4,%5,%6,%7},{%8,%9},{%0,%1,%2,%3};"
        : "+f"(c[0]), "+f"(c[1]), "+f"(c[2]), "+f"(c[3])
        : "r"(a[0]), "r"(a[1]), "r"(a[2]), "r"(a[3]), "r"(b[0]), "r"(b[1]));
}
__device__ __forceinline__ unsigned s2u(const void* p) {
    return (unsigned)__cvta_generic_to_shared(p);
}
__device__ __forceinline__ void ldsm4(unsigned* d, unsigned a) {
    asm volatile("ldmatrix.sync.aligned.m8n8.x4.shared.b16 {%0,%1,%2,%3},[%4];"
        : "=r"(d[0]), "=r"(d[1]), "=r"(d[2]), "=r"(d[3]) : "r"(a));
}
__device__ __forceinline__ void cpa16(unsigned d, const void* gp) {
    asm volatile("cp.async.cg.shared.global [%0], [%1], 16;" :: "r"(d), "l"(gp) : "memory");
}
__device__ __forceinline__ void cpcommit() { asm volatile("cp.async.commit_group;" ::: "memory"); }
__device__ __forceinline__ void cpwait1()  { asm volatile("cp.async.wait_group 1;" ::: "memory"); }
__device__ __forceinline__ void cpwait0()  { asm volatile("cp.async.wait_group 0;" ::: "memory"); }

__device__ __forceinline__ void bfsplit(float v, __nv_bfloat16& h, __nv_bfloat16& l) {
    h = __float2bfloat16(v);
    l = __float2bfloat16(v - __bfloat162float(h));
}

// consume one 128x128x32 staged tile: 2 k16 chunks, ldmatrix + 3-pass split MMA
__device__ __forceinline__ void consume_tile(
    const __nv_bfloat16* Ah, const __nv_bfloat16* Al,
    const __nv_bfloat16* Bh, const __nv_bfloat16* Bl,
    int wm, int wn, int lane, float acc[4][4][4])
{
    int ar = lane & 15, ac = (lane >> 4) * 8;
    int brow = ((lane >> 4) & 1) * 8 + (lane & 7);
    int bko  = ((lane >> 3) & 1) * 8;
#pragma unroll
    for (int ch = 0; ch < 2; ch++) {
        int ck = ch * 16;
        unsigned afh[4][4], afl[4][4], bfh[4][2], bfl[4][2];
#pragma unroll
        for (int mi = 0; mi < 4; mi++) {
            ldsm4(afh[mi], s2u(&Ah[(wm + mi * 16 + ar) * PIT + ck + ac]));
            ldsm4(afl[mi], s2u(&Al[(wm + mi * 16 + ar) * PIT + ck + ac]));
        }
#pragma unroll
        for (int j = 0; j < 2; j++) {
            unsigned bt[4];
            ldsm4(bt, s2u(&Bh[(wn + j * 16 + brow) * PIT + ck + bko]));
            bfh[2 * j][0] = bt[0]; bfh[2 * j][1] = bt[1];
            bfh[2 * j + 1][0] = bt[2]; bfh[2 * j + 1][1] = bt[3];
            ldsm4(bt, s2u(&Bl[(wn + j * 16 + brow) * PIT + ck + bko]));
            bfl[2 * j][0] = bt[0]; bfl[2 * j][1] = bt[1];
            bfl[2 * j + 1][0] = bt[2]; bfl[2 * j + 1][1] = bt[3];
        }
#pragma unroll
        for (int mi = 0; mi < 4; mi++)
#pragma unroll
            for (int ni = 0; ni < 4; ni++) {
                mma_bf16(acc[mi][ni], afh[mi], bfh[ni]);
                mma_bf16(acc[mi][ni], afh[mi], bfl[ni]);
                mma_bf16(acc[mi][ni], afl[mi], bfh[ni]);
            }
    }
}

// ---------------- unified split-bf16 tensor GEMM ----------------
// C[p,q] = gamma * sum_k (Ah+Al)[k + p*ldA] * (Bh+Bl)[k + q*ldB]   (+ alpha*X + beta*Y)
// optional bf16 split outputs Ch/Cl. flags: 1 = upper blocks only, 2 = triK (k < q0+128)
__global__ __launch_bounds__(256) void tgemm(
    const __nv_bfloat16* __restrict__ Ahg, const __nv_bfloat16* __restrict__ Alg, int ldA,
    const __nv_bfloat16* __restrict__ Bhg, const __nv_bfloat16* __restrict__ Blg, int ldB,
    const float* __restrict__ X, float alpha, const float* __restrict__ Y, float beta,
    float gamma, float* __restrict__ Cout,
    __nv_bfloat16* __restrict__ Ch, __nv_bfloat16* __restrict__ Cl, int ldc,
    int K, int flags)
{
    extern __shared__ __nv_bfloat16 smb[];
    int p0 = blockIdx.x * 128, q0 = blockIdx.y * 128;
    if ((flags & 1) && q0 < p0) return;
    int kmax = (flags & 2) ? (q0 + 128 < K ? q0 + 128 : K) : K;

    int tid = threadIdx.x, lane = tid & 31, warp = tid >> 5;
    int wm = (warp >> 2) * 64, wn = (warp & 3) * 32;
    int g = lane >> 2, tg = lane & 3;
    float acc[4][4][4];
#pragma unroll
    for (int i = 0; i < 4; i++)
#pragma unroll
        for (int j = 0; j < 4; j++)
#pragma unroll
            for (int k = 0; k < 4; k++) acc[i][j][k] = 0.f;

    int row = tid >> 1, kh = (tid & 1) * 16;
    const __nv_bfloat16* pAh = Ahg + (size_t)(p0 + row) * ldA + kh;
    const __nv_bfloat16* pAl = Alg + (size_t)(p0 + row) * ldA + kh;
    const __nv_bfloat16* pBh = Bhg + (size_t)(q0 + row) * ldB + kh;
    const __nv_bfloat16* pBl = Blg + (size_t)(q0 + row) * ldB + kh;
    unsigned dst0 = s2u(smb) + (unsigned)(row * PIT + kh) * 2;

#define STAGE(buf, k0) { unsigned d = dst0 + (buf) * 40960u; \
    cpa16(d,         pAh + (k0)); cpa16(d + 16,    pAh + (k0) + 8); \
    cpa16(d + 10240, pAl + (k0)); cpa16(d + 10256, pAl + (k0) + 8); \
    cpa16(d + 20480, pBh + (k0)); cpa16(d + 20496, pBh + (k0) + 8); \
    cpa16(d + 30720, pBl + (k0)); cpa16(d + 30736, pBl + (k0) + 8); \
    cpcommit(); }

    int niter = kmax / 32;
    STAGE(0, 0)
    for (int i = 0; i < niter; i++) {
        if (i + 1 < niter) { STAGE((i + 1) & 1, (i + 1) * 32) cpwait1(); }
        else cpwait0();
        __syncthreads();
        const __nv_bfloat16* base = smb + (i & 1) * 20480;
        consume_tile(base, base + 5120, base + 10240, base + 15360, wm, wn, lane, acc);
        __syncthreads();
    }
#undef STAGE

#pragma unroll
    for (int mi = 0; mi < 4; mi++)
#pragma unroll
        for (int ni = 0; ni < 4; ni++) {
            int p = p0 + wm + mi * 16 + g;
            int q = q0 + wn + ni * 8 + 2 * tg;
            float* c = acc[mi][ni];
            size_t o00 = (size_t)q * ldc + p;
            size_t o01 = (size_t)(q + 1) * ldc + p;
            float v00 = gamma * c[0], v01 = gamma * c[1];
            float v10 = gamma * c[2], v11 = gamma * c[3];
            if (X) { v00 += alpha * X[o00]; v01 += alpha * X[o01]; v10 += alpha * X[o00 + 8]; v11 += alpha * X[o01 + 8]; }
            if (Y) { v00 += beta * Y[o00]; v01 += beta * Y[o01]; v10 += beta * Y[o00 + 8]; v11 += beta * Y[o01 + 8]; }
            Cout[o00] = v00; Cout[o01] = v01; Cout[o00 + 8] = v10; Cout[o01 + 8] = v11;
            if (Ch) {
                __nv_bfloat16 h, l;
                bfsplit(v00, h, l); Ch[o00] = h; Cl[o00] = l;
                bfsplit(v01, h, l); Ch[o01] = h; Cl[o01] = l;
                bfsplit(v10, h, l); Ch[o00 + 8] = h; Cl[o00 + 8] = l;
                bfsplit(v11, h, l); Ch[o01 + 8] = h; Cl[o01 + 8] = l;
            }
        }
}

// ---------------- split / transpose-split kernels ----------------
__global__ void splitK(const float* __restrict__ x,
                       __nv_bfloat16* __restrict__ oh, __nv_bfloat16* __restrict__ ol) {
    size_t i = (size_t)blockIdx.x * 256 + threadIdx.x;
    __nv_bfloat16 h, l;
    bfsplit(x[i], h, l);
    oh[i] = h; ol[i] = l;
}

// X: 8192x2048 col-major (m-leading) -> XT[p*2048 + k] split
__global__ void tspK(const float* __restrict__ X,
                     __nv_bfloat16* __restrict__ oh, __nv_bfloat16* __restrict__ ol) {
    __shared__ float t[32][33];
    int p0 = blockIdx.x * 32, k0 = blockIdx.y * 32;
    int tx = threadIdx.x, ty = threadIdx.y;
#pragma unroll
    for (int j = 0; j < 32; j += 8)
        t[ty + j][tx] = X[(size_t)(k0 + ty + j) * RDIM + p0 + tx];
    __syncthreads();
#pragma unroll
    for (int j = 0; j < 32; j += 8) {
        float v = t[tx][ty + j];
        size_t o = (size_t)(p0 + ty + j) * CDIM + k0 + tx;
        __nv_bfloat16 h, l; bfsplit(v, h, l);
        oh[o] = h; ol[o] = l;
    }
}

__global__ void symSplitK(const float* __restrict__ in,
                          __nv_bfloat16* __restrict__ oh, __nv_bfloat16* __restrict__ ol) {
    int idx = blockIdx.x * 256 + threadIdx.x;
    int p = idx & (CDIM - 1), q = idx >> 11;
    float v = 0.5f * (in[idx] + in[(size_t)p * CDIM + q]);
    __nv_bfloat16 h, l; bfsplit(v, h, l);
    oh[idx] = h; ol[idx] = l;
}

// ---------------- FFMA GEMM (A^T x B) for Cholesky trailing updates ----------------
__global__ __launch_bounds__(256) void gemm_tn(
    const float* __restrict__ A, int lda, const float* __restrict__ B, int ldb,
    const float* __restrict__ Cin, float* __restrict__ Cout, int ldc,
    int K, float alpha, int upperOnly)
{
    int p0 = blockIdx.x * 64, q0 = blockIdx.y * 64;
    if (upperOnly && q0 < p0) return;
    __shared__ float As[16][68];
    __shared__ float Bs[16][68];
    int tid = threadIdx.x, tx = tid & 15, ty = tid >> 4;
    float acc[4][4];
#pragma unroll
    for (int a = 0; a < 4; a++)
#pragma unroll
        for (int b = 0; b < 4; b++) acc[a][b] = 0.f;
    for (int k0 = 0; k0 < K; k0 += 16) {
#pragma unroll
        for (int s2 = 0; s2 < 4; s2++) {
            int idx = tid + s2 * 256;
            int kk = idx & 15, pp = idx >> 4;
            As[kk][pp] = A[(size_t)(p0 + pp) * lda + (k0 + kk)];
            Bs[kk][pp] = B[(size_t)(q0 + pp) * ldb + (k0 + kk)];
        }
        __syncthreads();
#pragma unroll
        for (int kk = 0; kk < 16; kk++) {
            float4 av = *(const float4*)&As[kk][ty * 4];
            float4 bv = *(const float4*)&Bs[kk][tx * 4];
            float ar[4] = {av.x, av.y, av.z, av.w};
            float br[4] = {bv.x, bv.y, bv.z, bv.w};
#pragma unroll
            for (int a = 0; a < 4; a++)
#pragma unroll
                for (int b = 0; b < 4; b++)
                    acc[a][b] = fmaf(ar[a], br[b], acc[a][b]);
        }
        __syncthreads();
    }
#pragma unroll
    for (int a = 0; a < 4; a++)
#pragma unroll
        for (int b = 0; b < 4; b++) {
            int p = p0 + ty * 4 + a, q = q0 + tx * 4 + b;
            size_t o = (size_t)q * ldc + p;
            float v = alpha * acc[a][b];
            if (Cin) v += Cin[o];
            Cout[o] = v;
        }
}

// ---------------- batched FFMA NN GEMM for recursive triangular inverse ----------------
__global__ __launch_bounds__(256) void gemm_nn_b(
    const float* __restrict__ A, long long sA, int lda,
    const float* __restrict__ B, long long sB, int ldb,
    float* __restrict__ C, long long sC, int ldc, int K, float sgn)
{
    const float* Ap = A + (size_t)blockIdx.z * sA;
    const float* Bp = B + (size_t)blockIdx.z * sB;
    float* Cp = C + (size_t)blockIdx.z * sC;
    int i0 = blockIdx.x * 64, q0 = blockIdx.y * 64;
    __shared__ float As[16][68];
    __shared__ float Bs[16][68];
    int tid = threadIdx.x, tx = tid & 15, ty = tid >> 4;
    float acc[4][4];
#pragma unroll
    for (int a = 0; a < 4; a++)
#pragma unroll
        for (int b = 0; b < 4; b++) acc[a][b] = 0.f;
    for (int k0 = 0; k0 < K; k0 += 16) {
#pragma unroll
        for (int s2 = 0; s2 < 4; s2++) {
            int idx = tid + s2 * 256;
            int ii = idx & 63, kk = idx >> 6;
            As[kk][ii] = Ap[(size_t)(k0 + kk) * lda + (i0 + ii)];
            int kk2 = idx & 15, qq = idx >> 4;
            Bs[kk2][qq] = Bp[(size_t)(q0 + qq) * ldb + (k0 + kk2)];
        }
        __syncthreads();
#pragma unroll
        for (int kk = 0; kk < 16; kk++) {
            float4 av = *(const float4*)&As[kk][ty * 4];
            float4 bv = *(const float4*)&Bs[kk][tx * 4];
            float ar[4] = {av.x, av.y, av.z, av.w};
            float br[4] = {bv.x, bv.y, bv.z, bv.w};
#pragma unroll
            for (int a = 0; a < 4; a++)
#pragma unroll
                for (int b = 0; b < 4; b++)
                    acc[a][b] = fmaf(ar[a], br[b], acc[a][b]);
        }
        __syncthreads();
    }
#pragma unroll
    for (int a = 0; a < 4; a++)
#pragma unroll
        for (int b = 0; b < 4; b++) {
            int p = i0 + ty * 4 + a, q = q0 + tx * 4 + b;
            Cp[(size_t)q * ldc + p] = sgn * acc[a][b];
        }
}

// ---------------- small kernels ----------------
__global__ void zeroBufK(float* p) { p[(size_t)blockIdx.x * 256 + threadIdx.x] = 0.f; }

__global__ void rowsqK() {
    int i = blockIdx.x * 256 + threadIdx.x;
    int q0 = blockIdx.y * (CDIM / 16);
    float acc = 0.f;
    for (int q = q0; q < q0 + CDIM / 16; q++) {
        float v = g_G[(size_t)q * RDIM + i];
        acc += v * v;
    }
    g_rowp[(size_t)blockIdx.y * RDIM + i] = acc;
}
__global__ void rowcombK() {
    int i = blockIdx.x * 256 + threadIdx.x;
    float s = 0.f;
    for (int ch = 0; ch < 16; ch++) s += g_rowp[(size_t)ch * RDIM + i];
    g_dL[i] = s / (float)CDIM;
}
__global__ void colsqK() {
    __shared__ float red[256];
    int q = blockIdx.x, tid = threadIdx.x;
    const float* col = g_G + (size_t)q * RDIM;
    float acc = 0.f;
    for (int i = tid; i < RDIM; i += 256) { float v = col[i]; acc += v * v; }
    red[tid] = acc; __syncthreads();
    for (int s = 128; s > 0; s >>= 1) { if (tid < s) red[tid] += red[tid + s]; __syncthreads(); }
    if (tid == 0) g_dR[q] = red[0] / (float)RDIM;
}

__device__ __forceinline__ float sigm(float x) { return 1.f / (1.f + expf(-x)); }

__global__ __launch_bounds__(256) void lstmK(
    int N, const float* __restrict__ diag,
    const float* __restrict__ h0, const float* __restrict__ c0,
    const float* __restrict__ Wih0, const float* __restrict__ Whh0,
    const float* __restrict__ bih0, const float* __restrict__ bhh0,
    const float* __restrict__ Wih1, const float* __restrict__ Whh1,
    const float* __restrict__ bih1, const float* __restrict__ bhh1,
    const float* __restrict__ LW, const float* __restrict__ Lb,
    float* __restrict__ raw, float* __restrict__ part)
{
    __shared__ float sWih0[80], sB0[80], sB1[80];
    __shared__ float sWhh0[1600], sWih1[1600], sWhh1[1600];
    __shared__ float sLW[HID];
    int tid = threadIdx.x;
    for (int k = tid; k < 80; k += 256) {
        sWih0[k] = Wih0[k];
        sB0[k] = bih0[k] + bhh0[k];
        sB1[k] = bih1[k] + bhh1[k];
    }
    for (int k = tid; k < 1600; k += 256) {
        sWhh0[k] = Whh0[k]; sWih1[k] = Wih1[k]; sWhh1[k] = Whh1[k];
    }
    if (tid < HID) sLW[tid] = LW[tid];
    __syncthreads();

    int n = blockIdx.x * 256 + tid;
    float d = diag[n];
    float x = logf(fabsf(d)) * 0.1f;
    x = fminf(fmaxf(x, -1.f), 1.f);

    float hp[HID], h1[HID];
    const float* h0p = h0 + (size_t)n * HID;
    const float* c0p = c0 + (size_t)n * HID;
#pragma unroll
    for (int j = 0; j < HID; j++) hp[j] = h0p[j];
    for (int jh = 0; jh < HID; jh++) {
        float gi = sB0[jh]      + sWih0[jh] * x;
        float gf = sB0[20 + jh] + sWih0[20 + jh] * x;
        float gg = sB0[40 + jh] + sWih0[40 + jh] * x;
        float go = sB0[60 + jh] + sWih0[60 + jh] * x;
#pragma unroll
        for (int j = 0; j < HID; j++) {
            float hv = hp[j];
            gi = fmaf(sWhh0[jh * 20 + j], hv, gi);
            gf = fmaf(sWhh0[(20 + jh) * 20 + j], hv, gf);
            gg = fmaf(sWhh0[(40 + jh) * 20 + j], hv, gg);
            go = fmaf(sWhh0[(60 + jh) * 20 + j], hv, go);
        }
        float cc = sigm(gf) * c0p[jh] + sigm(gi) * tanhf(gg);
        h1[jh] = sigm(go) * tanhf(cc);
    }
    const float* h1p = h0 + (size_t)N * HID + (size_t)n * HID;
    const float* c1p = c0 + (size_t)N * HID + (size_t)n * HID;
    float hb[HID];
#pragma unroll
    for (int j = 0; j < HID; j++) hb[j] = h1p[j];
    float o = 0.f;
    for (int jh = 0; jh < HID; jh++) {
        float gi = sB1[jh], gf = sB1[20 + jh], gg = sB1[40 + jh], go = sB1[60 + jh];
#pragma unroll
        for (int j = 0; j < HID; j++) {
            float a = h1[j], b = hb[j];
            gi = fmaf(sWih1[jh * 20 + j], a, fmaf(sWhh1[jh * 20 + j], b, gi));
            gf = fmaf(sWih1[(20 + jh) * 20 + j], a, fmaf(sWhh1[(20 + jh) * 20 + j], b, gf));
            gg = fmaf(sWih1[(40 + jh) * 20 + j], a, fmaf(sWhh1[(40 + jh) * 20 + j], b, gg));
            go = fmaf(sWih1[(60 + jh) * 20 + j], a, fmaf(sWhh1[(60 + jh) * 20 + j], b, go));
        }
        float cc = sigm(gf) * c1p[jh] + sigm(gi) * tanhf(gg);
        float h2 = sigm(go) * tanhf(cc);
        o = fmaf(sLW[jh], h2, o);
    }
    float val = (o + Lb[0]) * 0.1f;
    raw[n] = val;

    __shared__ float red[256];
    red[tid] = val; __syncthreads();
    for (int s = 128; s > 0; s >>= 1) { if (tid < s) red[tid] += red[tid + s]; __syncthreads(); }
    if (tid == 0) part[blockIdx.x] = red[0];
}

__global__ void meansK() {
    if (threadIdx.x == 0) {
        float s = 0.f; for (int i = 0; i < 32; i++) s += g_partL[i];
        g_means[0] = s / (float)RDIM;
        float t = 0.f; for (int i = 0; i < 8; i++) t += g_partR[i];
        g_means[1] = t / (float)CDIM;
    }
}

__global__ void applyK(const float* __restrict__ raw, const float* __restrict__ before,
                       int mi, float* __restrict__ outv) {
    int i = blockIdx.x * 256 + threadIdx.x;
    outv[i] = fmaxf(raw[i] - g_means[mi] + 1.0f, before[i]);
}

__global__ void p0K() {
    size_t idx = (size_t)blockIdx.x * 256 + threadIdx.x;
    int i = (int)(idx & (RDIM - 1));
    int q = (int)(idx >> 13);
    float v = g_Lv[i] * g_G[idx] * g_Rv[q];
    g_P0[idx] = v;
    __nv_bfloat16 h, l; bfsplit(v, h, l);
    g_P0h[idx] = h; g_P0l[idx] = l;
}

// ---------------- Cholesky ----------------
// 256 threads: 64 cols x 4 row-groups for the trailing update
__global__ void cholDiagK(int k0) {
    __shared__ float S[64][65];
    int tid = threadIdx.x, t = tid & 63, w = tid >> 6;
    for (int e = tid; e < 4096; e += 256) {
        int a = e & 63, b = e >> 6;
        S[a][b] = g_Gram[(size_t)(k0 + b) * CDIM + (k0 + a)];
    }
    __syncthreads();
    for (int j = 0; j < 64; j++) {
        if (tid == 0) S[j][j] = sqrtf(S[j][j]);
        __syncthreads();
        float rjj = S[j][j];
        if (w == 0 && t > j) S[j][t] /= rjj;
        __syncthreads();
        if (t > j) {
            float sjt = S[j][t];
            for (int a = j + 1 + w; a <= t; a += 4) S[a][t] -= S[j][a] * sjt;
        }
        __syncthreads();
    }
    for (int e = tid; e < 4096; e += 256) {
        int a = e & 63, b = e >> 6;
        if (a <= b) g_Gram[(size_t)(k0 + b) * CDIM + (k0 + a)] = S[a][b];
    }
}

__global__ void cholTrsmK(int k0) {
    __shared__ float Rkk[64][65];
    __shared__ float Xs[64][65];
    int t = threadIdx.x;
    int qb = k0 + 64 + blockIdx.x * 64;
    for (int e = t; e < 4096; e += 64) {
        int a = e & 63, b = e >> 6;
        Rkk[a][b] = g_Gram[(size_t)(k0 + b) * CDIM + (k0 + a)];
        Xs[a][b]  = g_Gram[(size_t)(qb + b) * CDIM + (k0 + a)];
    }
    __syncthreads();
    for (int a = 0; a < 64; a++) {
        float sum = 0.f;
        for (int b = 0; b < a; b++) sum = fmaf(Rkk[b][a], Xs[b][t], sum);
        Xs[a][t] = (Xs[a][t] - sum) / Rkk[a][a];
    }
    __syncthreads();
    for (int e = t; e < 4096; e += 64) {
        int a = e & 63, b = e >> 6;
        g_Gram[(size_t)(qb + b) * CDIM + (k0 + a)] = Xs[a][b];
    }
}

__global__ void invDiagK() {
    int k0 = blockIdx.x * 64;
    __shared__ float U[64][65];
    __shared__ float Xs[64][65];
    int t = threadIdx.x;
    for (int e = t; e < 4096; e += 64) {
        int a = e & 63, b = e >> 6;
        U[a][b] = (a <= b) ? g_Gram[(size_t)(k0 + b) * CDIM + (k0 + a)] : 0.f;
        Xs[a][b] = 0.f;
    }
    __syncthreads();
    for (int a = 63; a >= 0; a--) {
        if (a <= t) {
            float sum = (a == t) ? 1.f : 0.f;
            for (int b = a + 1; b <= t; b++) sum = fmaf(-U[a][b], Xs[b][t], sum);
            Xs[a][t] = sum / U[a][a];
        }
    }
    __syncthreads();
    for (int e = t; e < 4096; e += 64) {
        int a = e & 63, b = e >> 6;
        g_Rinv[(size_t)(k0 + b) * CDIM + (k0 + a)] = Xs[a][b];
    }
}

extern "C" void kernel_launch(void* const* d_in, const int* in_sizes, int n_in,
                              void* d_out, int out_size) {
    const float* s   = (const float*)d_in[0];
    const float* sg  = (const float*)d_in[1];
    const float* Lh0 = (const float*)d_in[2];
    const float* Lc0 = (const float*)d_in[3];
    const float* Rh0 = (const float*)d_in[4];
    const float* Rc0 = (const float*)d_in[5];
    const float* Lbef = (const float*)d_in[6];
    const float* Rbef = (const float*)d_in[7];
    const float* Wih0 = (const float*)d_in[8];
    const float* Whh0 = (const float*)d_in[9];
    const float* bih0 = (const float*)d_in[10];
    const float* bhh0 = (const float*)d_in[11];
    const float* Wih1 = (const float*)d_in[12];
    const float* Whh1 = (const float*)d_in[13];
    const float* bih1 = (const float*)d_in[14];
    const float* bhh1 = (const float*)d_in[15];
    const float* LW = (const float*)d_in[16];
    const float* Lb = (const float*)d_in[17];
    const float* RW = (const float*)d_in[18];
    const float* Rb = (const float*)d_in[19];
    float* out = (float*)d_out;

    float *gG, *gP0, *gB, *gA, *gGram, *gRinv, *gT;
    float *gdL, *gdR, *glraw, *grraw, *gpartL, *gpartR, *gLv, *gRv;
    __nv_bfloat16 *sH, *sL, *sTh, *sTl, *sgH, *sgL, *P0h, *P0l;
    __nv_bfloat16 *BH, *BL, *BTh, *BTl, *AsH, *AsL, *RiH, *RiL;
    cudaGetSymbolAddress((void**)&gG, g_G);
    cudaGetSymbolAddress((void**)&gP0, g_P0);
    cudaGetSymbolAddress((void**)&gB, g_B);
    cudaGetSymbolAddress((void**)&gA, g_A);
    cudaGetSymbolAddress((void**)&gGram, g_Gram);
    cudaGetSymbolAddress((void**)&gRinv, g_Rinv);
    cudaGetSymbolAddress((void**)&gT, g_T);
    cudaGetSymbolAddress((void**)&gdL, g_dL);
    cudaGetSymbolAddress((void**)&gdR, g_dR);
    cudaGetSymbolAddress((void**)&glraw, g_lraw);
    cudaGetSymbolAddress((void**)&grraw, g_rraw);
    cudaGetSymbolAddress((void**)&gpartL, g_partL);
    cudaGetSymbolAddress((void**)&gpartR, g_partR);
    cudaGetSymbolAddress((void**)&gLv, g_Lv);
    cudaGetSymbolAddress((void**)&gRv, g_Rv);
    cudaGetSymbolAddress((void**)&sH, g_sH);
    cudaGetSymbolAddress((void**)&sL, g_sL);
    cudaGetSymbolAddress((void**)&sTh, g_sTh);
    cudaGetSymbolAddress((void**)&sTl, g_sTl);
    cudaGetSymbolAddress((void**)&sgH, g_sgH);
    cudaGetSymbolAddress((void**)&sgL, g_sgL);
    cudaGetSymbolAddress((void**)&P0h, g_P0h);
    cudaGetSymbolAddress((void**)&P0l, g_P0l);
    cudaGetSymbolAddress((void**)&BH, g_BH);
    cudaGetSymbolAddress((void**)&BL, g_BL);
    cudaGetSymbolAddress((void**)&BTh, g_BTh);
    cudaGetSymbolAddress((void**)&BTl, g_BTl);
    cudaGetSymbolAddress((void**)&AsH, g_AsH);
    cudaGetSymbolAddress((void**)&AsL, g_AsL);
    cudaGetSymbolAddress((void**)&RiH, g_RiH);
    cudaGetSymbolAddress((void**)&RiL, g_RiL);

    cudaFuncSetAttribute(tgemm, cudaFuncAttributeMaxDynamicSharedMemorySize, 81920);
    const int NELEM = RDIM * CDIM / 256;

    // 1-3: operand splits
    splitK<<<NELEM, 256>>>(s, sH, sL);
    splitK<<<NELEM, 256>>>(sg, sgH, sgL);
    tspK<<<dim3(RDIM / 32, CDIM / 32), dim3(32, 8)>>>(s, sTh, sTl);
    // 4 (profiled): A = 0.1 * s^T sg
    tgemm<<<dim3(16, 16), 256, 81920>>>(sH, sL, RDIM, sgH, sgL, RDIM,
        nullptr, 0.f, nullptr, 0.f, 0.1f, gA, nullptr, nullptr, CDIM, RDIM, 0);
    symSplitK<<<CDIM * CDIM / 256, 256>>>(gA, AsH, AsL);
    // G = 0.1*sg - s*As
    tgemm<<<dim3(64, 16), 256, 81920>>>(sTh, sTl, CDIM, AsH, AsL, CDIM,
        sg, 0.1f, nullptr, 0.f, -1.f, gG, nullptr, nullptr, RDIM, CDIM, 0);
    // Gram diagonals
    rowsqK<<<dim3(32, 16), 256>>>();
    rowcombK<<<32, 256>>>();
    colsqK<<<CDIM, 256>>>();
    // LSTMs
    lstmK<<<32, 256>>>(RDIM, gdL, Lh0, Lc0, Wih0, Whh0, bih0, bhh0, Wih1, Whh1, bih1, bhh1, LW, Lb, glraw, gpartL);
    lstmK<<<8, 256>>>(CDIM, gdR, Rh0, Rc0, Wih0, Whh0, bih0, bhh0, Wih1, Whh1, bih1, bhh1, RW, Rb, grraw, gpartR);
    meansK<<<1, 32>>>();
    applyK<<<32, 256>>>(glraw, Lbef, 0, gLv);
    applyK<<<8, 256>>>(grraw, Rbef, 1, gRv);
    // P0 = Lv . G . Rv (fp32 + split)
    p0K<<<NELEM, 256>>>();
    // A2 = s^T P0 ; As2 ; B = s*As2 + s - P0 (fp32 + split)
    tgemm<<<dim3(16, 16), 256, 81920>>>(sH, sL, RDIM, P0h, P0l, RDIM,
        nullptr, 0.f, nullptr, 0.f, 1.f, gA, nullptr, nullptr, CDIM, RDIM, 0);
    symSplitK<<<CDIM * CDIM / 256, 256>>>(gA, AsH, AsL);
    tgemm<<<dim3(64, 16), 256, 81920>>>(sTh, sTl, CDIM, AsH, AsL, CDIM,
        s, 1.f, gP0, -1.f, 1.f, gB, BH, BL, RDIM, CDIM, 0);
    tspK<<<dim3(RDIM / 32, CDIM / 32), dim3(32, 8)>>>(gB, BTh, BTl);
    // Gram = B^T B (upper)
    tgemm<<<dim3(16, 16), 256, 81920>>>(BH, BL, RDIM, BH, BL, RDIM,
        nullptr, 0.f, nullptr, 0.f, 1.f, gGram, nullptr, nullptr, CDIM, RDIM, 1);
    // blocked Cholesky
    for (int k = 0; k < NBLK; k++) {
        cholDiagK<<<1, 256>>>(k * 64);
        int nb = NBLK - 1 - k;
        if (nb > 0) {
            cholTrsmK<<<nb, 64>>>(k * 64);
            int r0 = (k + 1) * 64;
            const float* panel = gGram + (size_t)r0 * CDIM + k * 64;
            float* base = gGram + (size_t)r0 * CDIM + r0;
            gemm_tn<<<dim3(nb, nb), 256>>>(panel, CDIM, panel, CDIM, base, base, CDIM, 64, -1.f, 1);
        }
    }
    // Rinv via recursive doubling
    zeroBufK<<<CDIM * CDIM / 256, 256>>>(gRinv);
    invDiagK<<<NBLK, 64>>>();
    for (int b = 64; b <= 1024; b *= 2) {
        int npairs = CDIM / (2 * b);
        dim3 g1(b / 64, b / 64, npairs);
        long long strideP = (long long)2 * b * (CDIM + 1);
        gemm_nn_b<<<g1, 256>>>(gGram + (size_t)b * CDIM, strideP, CDIM,
                               gRinv + (size_t)b * CDIM + b, strideP, CDIM,
                               gT, (long long)b * b, b, b, 1.f);
        gemm_nn_b<<<g1, 256>>>(gRinv, strideP, CDIM,
                               gT, (long long)b * b, b,
                               gRinv + (size_t)b * CDIM, strideP, CDIM, b, -1.f);
    }
    splitK<<<CDIM * CDIM / 256, 256>>>(gRinv, RiH, RiL);
    // Q = B * Rinv -> out
    tgemm<<<dim3(64, 16), 256, 81920>>>(BTh, BTl, CDIM, RiH, RiL, CDIM,
        nullptr, 0.f, nullptr, 0.f, 1.f, out, nullptr, nullptr, RDIM, CDIM, 2);
}